// round 2
// baseline (speedup 1.0000x reference)
#include <cuda_runtime.h>
#include <cuda_bf16.h>
#include <cstdint>

// Problem constants (fixed by the dataset)
#define NMAX 50000
#define HID 128
#define NHEAD 4
#define CH 32

// ---------------- scratch (device globals; allocation-free) ----------------
__device__ float g_h[(size_t)NMAX * HID];     // projected features (pre-aggregation)
__device__ float g_feat[(size_t)NMAX * HID];  // layer output after ELU
__device__ float g_agg[(size_t)NMAX * HID];   // unnormalized aggregation
__device__ float g_as[(size_t)NMAX * NHEAD];  // alpha_src per node/head
__device__ float g_ad[(size_t)NMAX * NHEAD];  // alpha_dst per node/head
__device__ float g_m[(size_t)NMAX * NHEAD];   // segment max
__device__ float g_den[(size_t)NMAX * NHEAD]; // segment sum of exp

__device__ __forceinline__ float lrelu02(float v) { return v > 0.f ? v : 0.2f * v; }

__device__ __forceinline__ void atomicMaxF(float* a, float v) {
    if (v >= 0.f) atomicMax((int*)a, __float_as_int(v));
    else          atomicMin((unsigned int*)a, __float_as_uint(v));
}

// ---------------- GEMM: Out[n,128] = A[n,128] @ W[128,128] ----------------
// 64-row x 128-col tile per 256-thread block, 8x4 register micro-tile.
__global__ void gemm128(const float* __restrict__ A, const float* __restrict__ W,
                        float* __restrict__ Out, int n) {
    __shared__ float xs[64][32];
    __shared__ float ws[32][128];
    int tid = threadIdx.x;
    int tx = tid & 31;   // column group: 4 cols each -> 128 cols
    int ty = tid >> 5;   // row group: 8 rows each -> 64 rows
    int row0 = blockIdx.x * 64;

    float4 acc[8];
#pragma unroll
    for (int r = 0; r < 8; r++) acc[r] = make_float4(0.f, 0.f, 0.f, 0.f);

    for (int kc = 0; kc < 128; kc += 32) {
#pragma unroll
        for (int i = 0; i < 2; i++) {
            int idx = tid + i * 256;           // 512 float4 slots = 64x32 floats
            int r = idx >> 3;
            int kq = idx & 7;
            float4 v = make_float4(0.f, 0.f, 0.f, 0.f);
            if (row0 + r < n)
                v = *(const float4*)(A + (size_t)(row0 + r) * 128 + kc + kq * 4);
            *(float4*)&xs[r][kq * 4] = v;
        }
#pragma unroll
        for (int i = 0; i < 4; i++) {
            int idx = tid + i * 256;           // 1024 float4 = 32x128 floats
            int k = idx >> 5;
            int cq = idx & 31;
            *(float4*)&ws[k][cq * 4] = *(const float4*)(W + (size_t)(kc + k) * 128 + cq * 4);
        }
        __syncthreads();
#pragma unroll
        for (int k = 0; k < 32; k++) {
            float4 wv = *(float4*)&ws[k][tx * 4];
#pragma unroll
            for (int r = 0; r < 8; r++) {
                float xv = xs[ty * 8 + r][k];
                acc[r].x += xv * wv.x; acc[r].y += xv * wv.y;
                acc[r].z += xv * wv.z; acc[r].w += xv * wv.w;
            }
        }
        __syncthreads();
    }
#pragma unroll
    for (int r = 0; r < 8; r++) {
        int row = row0 + ty * 8 + r;
        if (row < n)
            *(float4*)(Out + (size_t)row * 128 + tx * 4) = acc[r];
    }
}

// ---------------- node prep: alpha_src/dst dots, seed m with self-loop, zero den/agg
// one warp per node; lane handles 4 consecutive features; head = lane/8
__global__ void node_prep(const float* __restrict__ a_s, const float* __restrict__ a_d, int n) {
    int w = (blockIdx.x * blockDim.x + threadIdx.x) >> 5;
    if (w >= n) return;
    int lane = threadIdx.x & 31;

    float4 hv = ((const float4*)(g_h + (size_t)w * 128))[lane];
    float4 asv = ((const float4*)a_s)[lane];
    float4 adv = ((const float4*)a_d)[lane];
    float ps = hv.x * asv.x + hv.y * asv.y + hv.z * asv.z + hv.w * asv.w;
    float pd = hv.x * adv.x + hv.y * adv.y + hv.z * adv.z + hv.w * adv.w;
#pragma unroll
    for (int o = 1; o < 8; o <<= 1) {
        ps += __shfl_xor_sync(0xffffffffu, ps, o);
        pd += __shfl_xor_sync(0xffffffffu, pd, o);
    }
    if ((lane & 7) == 0) {
        int hidx = lane >> 3;
        g_as[(size_t)w * 4 + hidx] = ps;
        g_ad[(size_t)w * 4 + hidx] = pd;
        g_m[(size_t)w * 4 + hidx]  = lrelu02(ps + pd);  // self-loop logit seeds the max
        g_den[(size_t)w * 4 + hidx] = 0.f;
    }
    ((float4*)(g_agg + (size_t)w * 128))[lane] = make_float4(0.f, 0.f, 0.f, 0.f);
}

// ---------------- edge pass 1: segment max (one thread per edge)
__global__ void edge_max(const int* __restrict__ ei, int E, int n) {
    int e = blockIdx.x * blockDim.x + threadIdx.x;
    if (e >= E) return;
    int src = ei[e];
    int dst = ei[(size_t)E + e];
    if ((unsigned)src >= (unsigned)n || (unsigned)dst >= (unsigned)n) return;
    float4 as = *(const float4*)(g_as + (size_t)src * 4);
    float4 ad = *(const float4*)(g_ad + (size_t)dst * 4);
    atomicMaxF(&g_m[(size_t)dst * 4 + 0], lrelu02(as.x + ad.x));
    atomicMaxF(&g_m[(size_t)dst * 4 + 1], lrelu02(as.y + ad.y));
    atomicMaxF(&g_m[(size_t)dst * 4 + 2], lrelu02(as.z + ad.z));
    atomicMaxF(&g_m[(size_t)dst * 4 + 3], lrelu02(as.w + ad.w));
}

// ---------------- edge pass 2: exp / denom / weighted scatter (one warp per edge)
__global__ void edge_accum(const int* __restrict__ ei, int E, int n) {
    int w = (blockIdx.x * blockDim.x + threadIdx.x) >> 5;
    if (w >= E) return;
    int lane = threadIdx.x & 31;
    int src = ei[w];
    int dst = ei[(size_t)E + w];
    if ((unsigned)src >= (unsigned)n || (unsigned)dst >= (unsigned)n) return;

    float ex = 0.f;
    if (lane < 4) {
        float e = lrelu02(g_as[(size_t)src * 4 + lane] + g_ad[(size_t)dst * 4 + lane]);
        ex = __expf(e - g_m[(size_t)dst * 4 + lane]);
        atomicAdd(&g_den[(size_t)dst * 4 + lane], ex);
    }
    float exl = __shfl_sync(0xffffffffu, ex, lane >> 3);  // head = lane/8

    float4 hv = ((const float4*)(g_h + (size_t)src * 128))[lane];
    float4 v = make_float4(hv.x * exl, hv.y * exl, hv.z * exl, hv.w * exl);
    atomicAdd(((float4*)(g_agg + (size_t)dst * 128)) + lane, v);
}

// ---------------- finalize: add self-loop, normalize, +bias, ELU (warp per node)
__global__ void node_fin(const float* __restrict__ b, float* __restrict__ outf, int n) {
    int w = (blockIdx.x * blockDim.x + threadIdx.x) >> 5;
    if (w >= n) return;
    int lane = threadIdx.x & 31;

    float ex = 0.f, inv = 0.f;
    if (lane < 4) {
        float e = lrelu02(g_as[(size_t)w * 4 + lane] + g_ad[(size_t)w * 4 + lane]);
        ex = __expf(e - g_m[(size_t)w * 4 + lane]);
        inv = 1.f / (g_den[(size_t)w * 4 + lane] + ex + 1e-16f);
    }
    float exl = __shfl_sync(0xffffffffu, ex, lane >> 3);
    float invl = __shfl_sync(0xffffffffu, inv, lane >> 3);

    float4 hv = ((const float4*)(g_h + (size_t)w * 128))[lane];
    float4 ag = ((const float4*)(g_agg + (size_t)w * 128))[lane];
    float4 bv = ((const float4*)b)[lane];
    float4 o;
    o.x = (ag.x + exl * hv.x) * invl + bv.x;
    o.y = (ag.y + exl * hv.y) * invl + bv.y;
    o.z = (ag.z + exl * hv.z) * invl + bv.z;
    o.w = (ag.w + exl * hv.w) * invl + bv.w;
    o.x = o.x > 0.f ? o.x : expm1f(o.x);
    o.y = o.y > 0.f ? o.y : expm1f(o.y);
    o.z = o.z > 0.f ? o.z : expm1f(o.z);
    o.w = o.w > 0.f ? o.w : expm1f(o.w);
    ((float4*)(outf + (size_t)w * 128))[lane] = o;
}

// ---------------- final FC: out[n,32] = feat[n,128] @ fc_w[128,32] + fc_b (warp per node)
__global__ void fc_kernel(const float* __restrict__ feat, const float* __restrict__ fw,
                          const float* __restrict__ fb, float* __restrict__ out, int n) {
    int w = (blockIdx.x * blockDim.x + threadIdx.x) >> 5;
    if (w >= n) return;
    int lane = threadIdx.x & 31;
    const float* fr = feat + (size_t)w * 128;
    float acc = fb[lane];
#pragma unroll 8
    for (int k = 0; k < 128; k++)
        acc += fr[k] * fw[(size_t)k * 32 + lane];
    out[(size_t)w * 32 + lane] = acc;
}

// ---------------- launch ----------------
extern "C" void kernel_launch(void* const* d_in, const int* in_sizes, int n_in,
                              void* d_out, int out_size) {
    const float* x    = (const float*)d_in[0];
    const int*   ei   = (const int*)d_in[1];     // int64 in reference -> int32 in harness
    const float* W1   = (const float*)d_in[2];
    const float* a_s1 = (const float*)d_in[3];
    const float* a_d1 = (const float*)d_in[4];
    const float* b1   = (const float*)d_in[5];
    const float* W2   = (const float*)d_in[6];
    const float* a_s2 = (const float*)d_in[7];
    const float* a_d2 = (const float*)d_in[8];
    const float* b2   = (const float*)d_in[9];
    const float* fc_w = (const float*)d_in[10];
    const float* fc_b = (const float*)d_in[11];
    float* out = (float*)d_out;

    int n = in_sizes[0] / HID;
    int E = in_sizes[1] / 2;

    float *p_h, *p_feat;
    cudaGetSymbolAddress((void**)&p_h, g_h);
    cudaGetSymbolAddress((void**)&p_feat, g_feat);

    int gemm_grid = (n + 63) / 64;
    int warp_grid = (n * 32 + 255) / 256;     // warp-per-node kernels
    int em_grid   = (E + 255) / 256;          // thread-per-edge
    int ea_grid   = (E + 7) / 8;              // warp-per-edge, 256-thread blocks

    // ---- layer 1 ----
    gemm128<<<gemm_grid, 256>>>(x, W1, p_h, n);
    node_prep<<<warp_grid, 256>>>(a_s1, a_d1, n);
    edge_max<<<em_grid, 256>>>(ei, E, n);
    edge_accum<<<ea_grid, 256>>>(ei, E, n);
    node_fin<<<warp_grid, 256>>>(b1, p_feat, n);

    // ---- layer 2 ----
    gemm128<<<gemm_grid, 256>>>(p_feat, W2, p_h, n);
    node_prep<<<warp_grid, 256>>>(a_s2, a_d2, n);
    edge_max<<<em_grid, 256>>>(ei, E, n);
    edge_accum<<<ea_grid, 256>>>(ei, E, n);
    node_fin<<<warp_grid, 256>>>(b2, p_feat, n);

    // ---- FC head ----
    fc_kernel<<<warp_grid, 256>>>(p_feat, fc_w, fc_b, out, n);
}

// round 3
// speedup vs baseline: 1.1713x; 1.1713x over previous
#include <cuda_runtime.h>
#include <cuda_bf16.h>
#include <cstdint>

#define NMAX 50000
#define EMAX 800000
#define HID 128
#define NHEAD 4

// ---------------- scratch (device globals; allocation-free) ----------------
__device__ float g_h[(size_t)NMAX * HID];       // projected features
__device__ float g_feat[(size_t)NMAX * HID];    // layer output after ELU
__device__ float g_as[(size_t)NMAX * NHEAD];    // alpha_src per node/head
__device__ float g_ad[(size_t)NMAX * NHEAD];    // alpha_dst per node/head
__device__ int   g_deg[NMAX];
__device__ int   g_rowptr[NMAX + 1];
__device__ int   g_cursor[NMAX];
__device__ int   g_csr_src[EMAX];

__device__ __forceinline__ float lrelu02(float v) { return v > 0.f ? v : 0.2f * v; }

// ================= CSR build =================
__global__ void k_zero_deg(int n) {
    int i = blockIdx.x * blockDim.x + threadIdx.x;
    if (i < n) g_deg[i] = 0;
}

__global__ void k_count(const int* __restrict__ ei, int E, int n) {
    int e = blockIdx.x * blockDim.x + threadIdx.x;
    if (e >= E) return;
    int dst = ei[(size_t)E + e];
    if ((unsigned)dst < (unsigned)n) atomicAdd(&g_deg[dst], 1);
}

// single-block exclusive scan (1024 threads, chunked)
__global__ void k_scan(int n) {
    __shared__ int sums[1024];
    int t = threadIdx.x;
    int chunk = (n + 1023) / 1024;
    int lo = t * chunk;
    int hi = min(lo + chunk, n);
    int s = 0;
    for (int i = lo; i < hi; i++) s += g_deg[i];
    sums[t] = s;
    __syncthreads();
    // Hillis-Steele inclusive scan
    for (int off = 1; off < 1024; off <<= 1) {
        int v = (t >= off) ? sums[t - off] : 0;
        __syncthreads();
        sums[t] += v;
        __syncthreads();
    }
    int run = (t == 0) ? 0 : sums[t - 1];
    for (int i = lo; i < hi; i++) {
        int d = g_deg[i];
        g_rowptr[i] = run;
        g_cursor[i] = run;
        run += d;
    }
    if (hi == n && lo < n) g_rowptr[n] = run;
    if (n <= lo && t == 0) g_rowptr[n] = sums[1023]; // safety (never for n=50000)
}

__global__ void k_scatter(const int* __restrict__ ei, int E, int n) {
    int e = blockIdx.x * blockDim.x + threadIdx.x;
    if (e >= E) return;
    int src = ei[e];
    int dst = ei[(size_t)E + e];
    if ((unsigned)src >= (unsigned)n || (unsigned)dst >= (unsigned)n) return;
    int pos = atomicAdd(&g_cursor[dst], 1);
    g_csr_src[pos] = src;
}

// ================= GEMM + alpha epilogue =================
// Out[n,128] = A[n,128] @ W[128,128]; also writes g_as/g_ad dots.
__global__ void gemm128(const float* __restrict__ A, const float* __restrict__ W,
                        float* __restrict__ Out,
                        const float* __restrict__ a_s, const float* __restrict__ a_d,
                        int n) {
    __shared__ float xs[64][32];
    __shared__ float ws[32][128];
    int tid = threadIdx.x;
    int tx = tid & 31;   // 4 cols each
    int ty = tid >> 5;   // 8 rows each
    int row0 = blockIdx.x * 64;

    float4 acc[8];
#pragma unroll
    for (int r = 0; r < 8; r++) acc[r] = make_float4(0.f, 0.f, 0.f, 0.f);

    for (int kc = 0; kc < 128; kc += 32) {
#pragma unroll
        for (int i = 0; i < 2; i++) {
            int idx = tid + i * 256;
            int r = idx >> 3;
            int kq = idx & 7;
            float4 v = make_float4(0.f, 0.f, 0.f, 0.f);
            if (row0 + r < n)
                v = *(const float4*)(A + (size_t)(row0 + r) * 128 + kc + kq * 4);
            *(float4*)&xs[r][kq * 4] = v;
        }
#pragma unroll
        for (int i = 0; i < 4; i++) {
            int idx = tid + i * 256;
            int k = idx >> 5;
            int cq = idx & 31;
            *(float4*)&ws[k][cq * 4] = *(const float4*)(W + (size_t)(kc + k) * 128 + cq * 4);
        }
        __syncthreads();
#pragma unroll
        for (int k = 0; k < 32; k++) {
            float4 wv = *(float4*)&ws[k][tx * 4];
#pragma unroll
            for (int r = 0; r < 8; r++) {
                float xv = xs[ty * 8 + r][k];
                acc[r].x += xv * wv.x; acc[r].y += xv * wv.y;
                acc[r].z += xv * wv.z; acc[r].w += xv * wv.w;
            }
        }
        __syncthreads();
    }

    float4 av = ((const float4*)a_s)[tx];
    float4 dv = ((const float4*)a_d)[tx];
    int head = tx >> 3;

#pragma unroll
    for (int r = 0; r < 8; r++) {
        int row = row0 + ty * 8 + r;
        if (row < n)
            *(float4*)(Out + (size_t)row * 128 + tx * 4) = acc[r];
        // alpha dots: reduce over the 8 lanes of this head
        float ps = acc[r].x * av.x + acc[r].y * av.y + acc[r].z * av.z + acc[r].w * av.w;
        float pd = acc[r].x * dv.x + acc[r].y * dv.y + acc[r].z * dv.z + acc[r].w * dv.w;
#pragma unroll
        for (int o = 1; o < 8; o <<= 1) {
            ps += __shfl_xor_sync(0xffffffffu, ps, o);
            pd += __shfl_xor_sync(0xffffffffu, pd, o);
        }
        if ((tx & 7) == 0 && row < n) {
            g_as[(size_t)row * 4 + head] = ps;
            g_ad[(size_t)row * 4 + head] = pd;
        }
    }
}

// ================= fused GAT aggregation (warp per dst node) =================
__global__ void gat_aggregate(const float* __restrict__ b, float* __restrict__ outf, int n) {
    int w = (blockIdx.x * blockDim.x + threadIdx.x) >> 5;
    if (w >= n) return;
    int lane = threadIdx.x & 31;
    int head = lane >> 3;

    int beg = g_rowptr[w];
    int end = g_rowptr[w + 1];

    float4 add = *(const float4*)(g_ad + (size_t)w * 4);
    float4 asd = *(const float4*)(g_as + (size_t)w * 4);
    float4 selfl;
    selfl.x = lrelu02(asd.x + add.x); selfl.y = lrelu02(asd.y + add.y);
    selfl.z = lrelu02(asd.z + add.z); selfl.w = lrelu02(asd.w + add.w);

    // ---- sweep 1: segment max (lanes parallel over edges) ----
    float4 m = selfl;
    for (int j = beg + lane; j < end; j += 32) {
        int s = g_csr_src[j];
        float4 a = *(const float4*)(g_as + (size_t)s * 4);
        m.x = fmaxf(m.x, lrelu02(a.x + add.x));
        m.y = fmaxf(m.y, lrelu02(a.y + add.y));
        m.z = fmaxf(m.z, lrelu02(a.z + add.z));
        m.w = fmaxf(m.w, lrelu02(a.w + add.w));
    }
#pragma unroll
    for (int o = 16; o > 0; o >>= 1) {
        m.x = fmaxf(m.x, __shfl_xor_sync(0xffffffffu, m.x, o));
        m.y = fmaxf(m.y, __shfl_xor_sync(0xffffffffu, m.y, o));
        m.z = fmaxf(m.z, __shfl_xor_sync(0xffffffffu, m.z, o));
        m.w = fmaxf(m.w, __shfl_xor_sync(0xffffffffu, m.w, o));
    }

    // ---- sweep 2: exp + den + weighted accumulation ----
    float4 den = make_float4(0.f, 0.f, 0.f, 0.f);
    float4 acc = make_float4(0.f, 0.f, 0.f, 0.f);

    for (int c = beg; c < end; c += 32) {
        int j = c + lane;
        bool valid = j < end;
        int s = valid ? g_csr_src[j] : 0;
        float4 ex = make_float4(0.f, 0.f, 0.f, 0.f);
        if (valid) {
            float4 a = *(const float4*)(g_as + (size_t)s * 4);
            ex.x = __expf(lrelu02(a.x + add.x) - m.x);
            ex.y = __expf(lrelu02(a.y + add.y) - m.y);
            ex.z = __expf(lrelu02(a.z + add.z) - m.z);
            ex.w = __expf(lrelu02(a.w + add.w) - m.w);
            den.x += ex.x; den.y += ex.y; den.z += ex.z; den.w += ex.w;
        }
        int cnt = min(32, end - c);
        for (int k = 0; k < cnt; k++) {
            int sk   = __shfl_sync(0xffffffffu, s, k);
            float e0 = __shfl_sync(0xffffffffu, ex.x, k);
            float e1 = __shfl_sync(0xffffffffu, ex.y, k);
            float e2 = __shfl_sync(0xffffffffu, ex.z, k);
            float e3 = __shfl_sync(0xffffffffu, ex.w, k);
            float ek = (head < 2) ? (head == 0 ? e0 : e1) : (head == 2 ? e2 : e3);
            float4 hv = ((const float4*)(g_h + (size_t)sk * 128))[lane];
            acc.x += ek * hv.x; acc.y += ek * hv.y;
            acc.z += ek * hv.z; acc.w += ek * hv.w;
        }
    }
    // reduce den across lanes
#pragma unroll
    for (int o = 16; o > 0; o >>= 1) {
        den.x += __shfl_xor_sync(0xffffffffu, den.x, o);
        den.y += __shfl_xor_sync(0xffffffffu, den.y, o);
        den.z += __shfl_xor_sync(0xffffffffu, den.z, o);
        den.w += __shfl_xor_sync(0xffffffffu, den.w, o);
    }

    // self-loop contribution
    float4 exs;
    exs.x = __expf(selfl.x - m.x); exs.y = __expf(selfl.y - m.y);
    exs.z = __expf(selfl.z - m.z); exs.w = __expf(selfl.w - m.w);
    den.x += exs.x; den.y += exs.y; den.z += exs.z; den.w += exs.w;

    float es = (head < 2) ? (head == 0 ? exs.x : exs.y) : (head == 2 ? exs.z : exs.w);
    float dn = (head < 2) ? (head == 0 ? den.x : den.y) : (head == 2 ? den.z : den.w);
    float inv = 1.f / (dn + 1e-16f);

    float4 hself = ((const float4*)(g_h + (size_t)w * 128))[lane];
    float4 bv = ((const float4*)b)[lane];
    float4 o;
    o.x = (acc.x + es * hself.x) * inv + bv.x;
    o.y = (acc.y + es * hself.y) * inv + bv.y;
    o.z = (acc.z + es * hself.z) * inv + bv.z;
    o.w = (acc.w + es * hself.w) * inv + bv.w;
    o.x = o.x > 0.f ? o.x : expm1f(o.x);
    o.y = o.y > 0.f ? o.y : expm1f(o.y);
    o.z = o.z > 0.f ? o.z : expm1f(o.z);
    o.w = o.w > 0.f ? o.w : expm1f(o.w);
    ((float4*)(outf + (size_t)w * 128))[lane] = o;
}

// ================= FC head =================
__global__ void fc_kernel(const float* __restrict__ feat, const float* __restrict__ fw,
                          const float* __restrict__ fb, float* __restrict__ out, int n) {
    int w = (blockIdx.x * blockDim.x + threadIdx.x) >> 5;
    if (w >= n) return;
    int lane = threadIdx.x & 31;
    const float* fr = feat + (size_t)w * 128;
    float acc = fb[lane];
#pragma unroll 8
    for (int k = 0; k < 128; k++)
        acc += fr[k] * fw[(size_t)k * 32 + lane];
    out[(size_t)w * 32 + lane] = acc;
}

// ================= launch =================
extern "C" void kernel_launch(void* const* d_in, const int* in_sizes, int n_in,
                              void* d_out, int out_size) {
    const float* x    = (const float*)d_in[0];
    const int*   ei   = (const int*)d_in[1];
    const float* W1   = (const float*)d_in[2];
    const float* a_s1 = (const float*)d_in[3];
    const float* a_d1 = (const float*)d_in[4];
    const float* b1   = (const float*)d_in[5];
    const float* W2   = (const float*)d_in[6];
    const float* a_s2 = (const float*)d_in[7];
    const float* a_d2 = (const float*)d_in[8];
    const float* b2   = (const float*)d_in[9];
    const float* fc_w = (const float*)d_in[10];
    const float* fc_b = (const float*)d_in[11];
    float* out = (float*)d_out;

    int n = in_sizes[0] / HID;
    int E = in_sizes[1] / 2;

    float *p_h, *p_feat;
    cudaGetSymbolAddress((void**)&p_h, g_h);
    cudaGetSymbolAddress((void**)&p_feat, g_feat);

    int gemm_grid = (n + 63) / 64;
    int warp_grid = (n * 32 + 255) / 256;
    int edge_grid = (E + 255) / 256;

    // ---- CSR build (by destination) ----
    k_zero_deg<<<(n + 255) / 256, 256>>>(n);
    k_count<<<edge_grid, 256>>>(ei, E, n);
    k_scan<<<1, 1024>>>(n);
    k_scatter<<<edge_grid, 256>>>(ei, E, n);

    // ---- layer 1 ----
    gemm128<<<gemm_grid, 256>>>(x, W1, p_h, a_s1, a_d1, n);
    gat_aggregate<<<warp_grid, 256>>>(b1, p_feat, n);

    // ---- layer 2 ----
    gemm128<<<gemm_grid, 256>>>(p_feat, W2, p_h, a_s2, a_d2, n);
    gat_aggregate<<<warp_grid, 256>>>(b2, p_feat, n);

    // ---- FC head ----
    fc_kernel<<<warp_grid, 256>>>(p_feat, fc_w, fc_b, out, n);
}

// round 5
// speedup vs baseline: 1.2969x; 1.1072x over previous
#include <cuda_runtime.h>
#include <cuda_bf16.h>
#include <cstdint>

#define NMAX 50000
#define EMAX 800000
#define HID 128
#define NHEAD 4

// ---------------- scratch (device globals; allocation-free) ----------------
__device__ float g_h[(size_t)NMAX * HID];       // projected features
__device__ float g_feat[(size_t)NMAX * HID];    // layer-1 output after ELU
__device__ float g_as[(size_t)NMAX * NHEAD];    // alpha_src per node/head
__device__ float g_ad[(size_t)NMAX * NHEAD];    // alpha_dst per node/head
__device__ float g_gmax[2 * NHEAD];             // global per-head max of alpha_src (2 layers)
__device__ int   g_deg[NMAX];
__device__ int   g_rowptr[NMAX + 1];
__device__ int   g_cursor[NMAX];
__device__ int   g_csr_src[EMAX];

__device__ __forceinline__ float lrelu02(float v) { return v > 0.f ? v : 0.2f * v; }

__device__ __forceinline__ void atomicMaxF(float* a, float v) {
    if (v >= 0.f) atomicMax((int*)a, __float_as_int(v));
    else          atomicMin((unsigned int*)a, __float_as_uint(v));
}

// ================= CSR build =================
__global__ void k_zero_deg(int n) {
    int i = blockIdx.x * blockDim.x + threadIdx.x;
    if (i < n) g_deg[i] = 0;
    if (i < 2 * NHEAD) g_gmax[i] = -1e30f;
}

__global__ void k_count(const int* __restrict__ ei, int E, int n) {
    int e = blockIdx.x * blockDim.x + threadIdx.x;
    if (e >= E) return;
    int dst = ei[(size_t)E + e];
    if ((unsigned)dst < (unsigned)n) atomicAdd(&g_deg[dst], 1);
}

// single-block exclusive scan (1024 threads, chunked)
__global__ void k_scan(int n) {
    __shared__ int sums[1024];
    int t = threadIdx.x;
    int chunk = (n + 1023) / 1024;
    int lo = t * chunk;
    int hi = min(lo + chunk, n);
    int s = 0;
    for (int i = lo; i < hi; i++) s += g_deg[i];
    sums[t] = s;
    __syncthreads();
    for (int off = 1; off < 1024; off <<= 1) {
        int v = (t >= off) ? sums[t - off] : 0;
        __syncthreads();
        sums[t] += v;
        __syncthreads();
    }
    int run = (t == 0) ? 0 : sums[t - 1];
    for (int i = lo; i < hi; i++) {
        int d = g_deg[i];
        g_rowptr[i] = run;
        g_cursor[i] = run;
        run += d;
    }
    if (hi == n && lo < n) g_rowptr[n] = run;
}

__global__ void k_scatter(const int* __restrict__ ei, int E, int n) {
    int e = blockIdx.x * blockDim.x + threadIdx.x;
    if (e >= E) return;
    int src = ei[e];
    int dst = ei[(size_t)E + e];
    if ((unsigned)src >= (unsigned)n || (unsigned)dst >= (unsigned)n) return;
    int pos = atomicAdd(&g_cursor[dst], 1);
    g_csr_src[pos] = src;
}

// ================= global per-head max of alpha_src =================
__global__ void k_gmax(float* __restrict__ out4, int n) {
    __shared__ float red[8][4];
    int i = blockIdx.x * blockDim.x + threadIdx.x;
    int lane = threadIdx.x & 31;
    int wp = threadIdx.x >> 5;
    float4 v = (i < n) ? ((const float4*)g_as)[i]
                       : make_float4(-1e30f, -1e30f, -1e30f, -1e30f);
#pragma unroll
    for (int o = 16; o > 0; o >>= 1) {
        v.x = fmaxf(v.x, __shfl_xor_sync(0xffffffffu, v.x, o));
        v.y = fmaxf(v.y, __shfl_xor_sync(0xffffffffu, v.y, o));
        v.z = fmaxf(v.z, __shfl_xor_sync(0xffffffffu, v.z, o));
        v.w = fmaxf(v.w, __shfl_xor_sync(0xffffffffu, v.w, o));
    }
    if (lane == 0) { red[wp][0] = v.x; red[wp][1] = v.y; red[wp][2] = v.z; red[wp][3] = v.w; }
    __syncthreads();
    if (threadIdx.x < 4) {
        float m = red[0][threadIdx.x];
#pragma unroll
        for (int r = 1; r < 8; r++) m = fmaxf(m, red[r][threadIdx.x]);
        atomicMaxF(&out4[threadIdx.x], m);
    }
}

// ================= GEMM + alpha epilogue =================
__global__ void gemm128(const float* __restrict__ A, const float* __restrict__ W,
                        float* __restrict__ Out,
                        const float* __restrict__ a_s, const float* __restrict__ a_d,
                        int n) {
    __shared__ float xs[64][32];
    __shared__ float ws[32][128];
    int tid = threadIdx.x;
    int tx = tid & 31;
    int ty = tid >> 5;
    int row0 = blockIdx.x * 64;

    float4 acc[8];
#pragma unroll
    for (int r = 0; r < 8; r++) acc[r] = make_float4(0.f, 0.f, 0.f, 0.f);

    for (int kc = 0; kc < 128; kc += 32) {
#pragma unroll
        for (int i = 0; i < 2; i++) {
            int idx = tid + i * 256;
            int r = idx >> 3;
            int kq = idx & 7;
            float4 v = make_float4(0.f, 0.f, 0.f, 0.f);
            if (row0 + r < n)
                v = *(const float4*)(A + (size_t)(row0 + r) * 128 + kc + kq * 4);
            *(float4*)&xs[r][kq * 4] = v;
        }
#pragma unroll
        for (int i = 0; i < 4; i++) {
            int idx = tid + i * 256;
            int k = idx >> 5;
            int cq = idx & 31;
            *(float4*)&ws[k][cq * 4] = *(const float4*)(W + (size_t)(kc + k) * 128 + cq * 4);
        }
        __syncthreads();
#pragma unroll
        for (int k = 0; k < 32; k++) {
            float4 wv = *(float4*)&ws[k][tx * 4];
#pragma unroll
            for (int r = 0; r < 8; r++) {
                float xv = xs[ty * 8 + r][k];
                acc[r].x += xv * wv.x; acc[r].y += xv * wv.y;
                acc[r].z += xv * wv.z; acc[r].w += xv * wv.w;
            }
        }
        __syncthreads();
    }

    float4 av = ((const float4*)a_s)[tx];
    float4 dv = ((const float4*)a_d)[tx];
    int head = tx >> 3;

#pragma unroll
    for (int r = 0; r < 8; r++) {
        int row = row0 + ty * 8 + r;
        if (row < n)
            *(float4*)(Out + (size_t)row * 128 + tx * 4) = acc[r];
        float ps = acc[r].x * av.x + acc[r].y * av.y + acc[r].z * av.z + acc[r].w * av.w;
        float pd = acc[r].x * dv.x + acc[r].y * dv.y + acc[r].z * dv.z + acc[r].w * dv.w;
#pragma unroll
        for (int o = 1; o < 8; o <<= 1) {
            ps += __shfl_xor_sync(0xffffffffu, ps, o);
            pd += __shfl_xor_sync(0xffffffffu, pd, o);
        }
        if ((tx & 7) == 0 && row < n) {
            g_as[(size_t)row * 4 + head] = ps;
            g_ad[(size_t)row * 4 + head] = pd;
        }
    }
}

// ================= aggregate body (defined BEFORE its users) =================
__device__ __forceinline__ void run_node(const float* __restrict__ b, float* __restrict__ outf,
                                         const float* __restrict__ gmax4,
                                         const float* __restrict__ sfw,
                                         const float* __restrict__ fcb, int n) {
    int w = (blockIdx.x * blockDim.x + threadIdx.x) >> 5;
    if (w >= n) return;
    int lane = threadIdx.x & 31;
    int head = lane >> 3;

    int beg = g_rowptr[w];
    int end = g_rowptr[w + 1];

    float4 add = *(const float4*)(g_ad + (size_t)w * 4);
    float4 asd = *(const float4*)(g_as + (size_t)w * 4);
    float4 gm  = *(const float4*)gmax4;
    float4 s4;
    s4.x = lrelu02(gm.x + add.x); s4.y = lrelu02(gm.y + add.y);
    s4.z = lrelu02(gm.z + add.z); s4.w = lrelu02(gm.w + add.w);

    float4 den = make_float4(0.f, 0.f, 0.f, 0.f);
    float4 acc = make_float4(0.f, 0.f, 0.f, 0.f);

    for (int c = beg; c < end; c += 32) {
        int j = c + lane;
        bool valid = j < end;
        int sidx = valid ? g_csr_src[j] : 0;
        float4 ex = make_float4(0.f, 0.f, 0.f, 0.f);
        if (valid) {
            float4 a = *(const float4*)(g_as + (size_t)sidx * 4);
            ex.x = __expf(lrelu02(a.x + add.x) - s4.x);
            ex.y = __expf(lrelu02(a.y + add.y) - s4.y);
            ex.z = __expf(lrelu02(a.z + add.z) - s4.z);
            ex.w = __expf(lrelu02(a.w + add.w) - s4.w);
            den.x += ex.x; den.y += ex.y; den.z += ex.z; den.w += ex.w;
        }
        int cnt = min(32, end - c);
        int k = 0;
        for (; k + 4 <= cnt; k += 4) {
            int   sk0 = __shfl_sync(0xffffffffu, sidx, k);
            int   sk1 = __shfl_sync(0xffffffffu, sidx, k + 1);
            int   sk2 = __shfl_sync(0xffffffffu, sidx, k + 2);
            int   sk3 = __shfl_sync(0xffffffffu, sidx, k + 3);
            float a0 = __shfl_sync(0xffffffffu, ex.x, k), b0 = __shfl_sync(0xffffffffu, ex.y, k),
                  c0 = __shfl_sync(0xffffffffu, ex.z, k), d0 = __shfl_sync(0xffffffffu, ex.w, k);
            float a1 = __shfl_sync(0xffffffffu, ex.x, k+1), b1 = __shfl_sync(0xffffffffu, ex.y, k+1),
                  c1 = __shfl_sync(0xffffffffu, ex.z, k+1), d1 = __shfl_sync(0xffffffffu, ex.w, k+1);
            float a2 = __shfl_sync(0xffffffffu, ex.x, k+2), b2 = __shfl_sync(0xffffffffu, ex.y, k+2),
                  c2 = __shfl_sync(0xffffffffu, ex.z, k+2), d2 = __shfl_sync(0xffffffffu, ex.w, k+2);
            float a3 = __shfl_sync(0xffffffffu, ex.x, k+3), b3 = __shfl_sync(0xffffffffu, ex.y, k+3),
                  c3 = __shfl_sync(0xffffffffu, ex.z, k+3), d3 = __shfl_sync(0xffffffffu, ex.w, k+3);
            float e0 = head < 2 ? (head == 0 ? a0 : b0) : (head == 2 ? c0 : d0);
            float e1 = head < 2 ? (head == 0 ? a1 : b1) : (head == 2 ? c1 : d1);
            float e2 = head < 2 ? (head == 0 ? a2 : b2) : (head == 2 ? c2 : d2);
            float e3 = head < 2 ? (head == 0 ? a3 : b3) : (head == 2 ? c3 : d3);
            float4 h0 = ((const float4*)(g_h + (size_t)sk0 * 128))[lane];
            float4 h1 = ((const float4*)(g_h + (size_t)sk1 * 128))[lane];
            float4 h2 = ((const float4*)(g_h + (size_t)sk2 * 128))[lane];
            float4 h3 = ((const float4*)(g_h + (size_t)sk3 * 128))[lane];
            acc.x += e0 * h0.x + e1 * h1.x + e2 * h2.x + e3 * h3.x;
            acc.y += e0 * h0.y + e1 * h1.y + e2 * h2.y + e3 * h3.y;
            acc.z += e0 * h0.z + e1 * h1.z + e2 * h2.z + e3 * h3.z;
            acc.w += e0 * h0.w + e1 * h1.w + e2 * h2.w + e3 * h3.w;
        }
        for (; k < cnt; k++) {
            int   sk = __shfl_sync(0xffffffffu, sidx, k);
            float a0 = __shfl_sync(0xffffffffu, ex.x, k), b0 = __shfl_sync(0xffffffffu, ex.y, k),
                  c0 = __shfl_sync(0xffffffffu, ex.z, k), d0 = __shfl_sync(0xffffffffu, ex.w, k);
            float ek = head < 2 ? (head == 0 ? a0 : b0) : (head == 2 ? c0 : d0);
            float4 hv = ((const float4*)(g_h + (size_t)sk * 128))[lane];
            acc.x += ek * hv.x; acc.y += ek * hv.y;
            acc.z += ek * hv.z; acc.w += ek * hv.w;
        }
    }
#pragma unroll
    for (int o = 16; o > 0; o >>= 1) {
        den.x += __shfl_xor_sync(0xffffffffu, den.x, o);
        den.y += __shfl_xor_sync(0xffffffffu, den.y, o);
        den.z += __shfl_xor_sync(0xffffffffu, den.z, o);
        den.w += __shfl_xor_sync(0xffffffffu, den.w, o);
    }

    // self-loop contribution
    float4 exs;
    exs.x = __expf(lrelu02(asd.x + add.x) - s4.x);
    exs.y = __expf(lrelu02(asd.y + add.y) - s4.y);
    exs.z = __expf(lrelu02(asd.z + add.z) - s4.z);
    exs.w = __expf(lrelu02(asd.w + add.w) - s4.w);
    den.x += exs.x; den.y += exs.y; den.z += exs.z; den.w += exs.w;

    float es = head < 2 ? (head == 0 ? exs.x : exs.y) : (head == 2 ? exs.z : exs.w);
    float dn = head < 2 ? (head == 0 ? den.x : den.y) : (head == 2 ? den.z : den.w);
    float inv = 1.f / (dn + 1e-16f);

    float4 hself = ((const float4*)(g_h + (size_t)w * 128))[lane];
    float4 bv = ((const float4*)b)[lane];
    float4 o;
    o.x = (acc.x + es * hself.x) * inv + bv.x;
    o.y = (acc.y + es * hself.y) * inv + bv.y;
    o.z = (acc.z + es * hself.z) * inv + bv.z;
    o.w = (acc.w + es * hself.w) * inv + bv.w;
    o.x = o.x > 0.f ? o.x : expm1f(o.x);
    o.y = o.y > 0.f ? o.y : expm1f(o.y);
    o.z = o.z > 0.f ? o.z : expm1f(o.z);
    o.w = o.w > 0.f ? o.w : expm1f(o.w);

    if (sfw == nullptr) {
        ((float4*)(outf + (size_t)w * 128))[lane] = o;
    } else {
        // fused FC: out[w, lane] = fcb[lane] + sum_k feat[k] * fc_w[k, lane]
        float fa = fcb[lane];
#pragma unroll 8
        for (int r = 0; r < 32; r++) {
            float fx = __shfl_sync(0xffffffffu, o.x, r);
            float fy = __shfl_sync(0xffffffffu, o.y, r);
            float fz = __shfl_sync(0xffffffffu, o.z, r);
            float fw2 = __shfl_sync(0xffffffffu, o.w, r);
            int kb = r * 4;
            fa += fx * sfw[kb * 32 + lane] + fy * sfw[(kb + 1) * 32 + lane]
                + fz * sfw[(kb + 2) * 32 + lane] + fw2 * sfw[(kb + 3) * 32 + lane];
        }
        outf[(size_t)w * 32 + lane] = fa;
    }
}

// ================= fused GAT aggregation (warp per dst node) =================
template <bool FUSE>
__global__ void gat_aggregate(const float* __restrict__ b, float* __restrict__ outf,
                              const float* __restrict__ gmax4,
                              const float* __restrict__ fcw, const float* __restrict__ fcb,
                              int n) {
    if constexpr (FUSE) {
        __shared__ float sfw[HID * 32];
#pragma unroll
        for (int i = 0; i < 4; i++)
            ((float4*)sfw)[threadIdx.x + i * 256] = ((const float4*)fcw)[threadIdx.x + i * 256];
        __syncthreads();
        run_node(b, outf, gmax4, sfw, fcb, n);
    } else {
        run_node(b, outf, gmax4, (const float*)nullptr, fcb, n);
    }
}

// ================= launch =================
extern "C" void kernel_launch(void* const* d_in, const int* in_sizes, int n_in,
                              void* d_out, int out_size) {
    const float* x    = (const float*)d_in[0];
    const int*   ei   = (const int*)d_in[1];
    const float* W1   = (const float*)d_in[2];
    const float* a_s1 = (const float*)d_in[3];
    const float* a_d1 = (const float*)d_in[4];
    const float* b1   = (const float*)d_in[5];
    const float* W2   = (const float*)d_in[6];
    const float* a_s2 = (const float*)d_in[7];
    const float* a_d2 = (const float*)d_in[8];
    const float* b2   = (const float*)d_in[9];
    const float* fc_w = (const float*)d_in[10];
    const float* fc_b = (const float*)d_in[11];
    float* out = (float*)d_out;

    int n = in_sizes[0] / HID;
    int E = in_sizes[1] / 2;

    float *p_h, *p_feat, *p_gmax;
    cudaGetSymbolAddress((void**)&p_h, g_h);
    cudaGetSymbolAddress((void**)&p_feat, g_feat);
    cudaGetSymbolAddress((void**)&p_gmax, g_gmax);

    int gemm_grid = (n + 63) / 64;
    int warp_grid = (n * 32 + 255) / 256;
    int edge_grid = (E + 255) / 256;
    int node_grid = (n + 255) / 256;

    // ---- CSR build (by destination) + gmax init ----
    k_zero_deg<<<node_grid, 256>>>(n);
    k_count<<<edge_grid, 256>>>(ei, E, n);
    k_scan<<<1, 1024>>>(n);
    k_scatter<<<edge_grid, 256>>>(ei, E, n);

    // ---- layer 1 ----
    gemm128<<<gemm_grid, 256>>>(x, W1, p_h, a_s1, a_d1, n);
    k_gmax<<<node_grid, 256>>>(p_gmax, n);
    gat_aggregate<false><<<warp_grid, 256>>>(b1, p_feat, p_gmax, nullptr, nullptr, n);

    // ---- layer 2 (FC fused into aggregation) ----
    gemm128<<<gemm_grid, 256>>>(p_feat, W2, p_h, a_s2, a_d2, n);
    k_gmax<<<node_grid, 256>>>(p_gmax + 4, n);
    gat_aggregate<true><<<warp_grid, 256>>>(b2, out, p_gmax + 4, fc_w, fc_b, n);
}

// round 6
// speedup vs baseline: 1.3297x; 1.0253x over previous
#include <cuda_runtime.h>
#include <cuda_bf16.h>
#include <cstdint>

#define NMAX 50000
#define EMAX 800000
#define HID 128
#define NHEAD 4

// ---------------- scratch (device globals; allocation-free) ----------------
__device__ float g_h[(size_t)NMAX * HID];       // projected features
__device__ float g_feat[(size_t)NMAX * HID];    // layer-1 output after ELU
__device__ float g_as[(size_t)NMAX * NHEAD];    // alpha_src per node/head
__device__ float g_ad[(size_t)NMAX * NHEAD];    // alpha_dst per node/head
__device__ float g_gmax[2 * NHEAD];             // global per-head max of alpha_src (2 layers)
__device__ int   g_deg[NMAX];
__device__ int   g_rowptr[NMAX + 1];
__device__ int   g_cursor[NMAX];
__device__ int   g_csr_src[EMAX];

__device__ __forceinline__ float lrelu02(float v) { return v > 0.f ? v : 0.2f * v; }

__device__ __forceinline__ void atomicMaxF(float* a, float v) {
    if (v >= 0.f) atomicMax((int*)a, __float_as_int(v));
    else          atomicMin((unsigned int*)a, __float_as_uint(v));
}

// ================= CSR build (runs on secondary stream) =================
__global__ void k_zero_deg(int n) {
    int i = blockIdx.x * blockDim.x + threadIdx.x;
    if (i < n) g_deg[i] = 0;
    if (i < 2 * NHEAD) g_gmax[i] = -1e30f;
}

__global__ void k_count(const int* __restrict__ ei, int E, int n) {
    int e = blockIdx.x * blockDim.x + threadIdx.x;
    if (e >= E) return;
    int dst = ei[(size_t)E + e];
    if ((unsigned)dst < (unsigned)n) atomicAdd(&g_deg[dst], 1);
}

// single-block exclusive scan (1024 threads, chunked, int4-vectorized sums)
__global__ void k_scan(int n) {
    __shared__ int sums[1024];
    int t = threadIdx.x;
    int chunk = (((n + 1023) / 1024) + 3) & ~3;   // multiple of 4
    int lo = min(t * chunk, n);
    int hi = min(lo + chunk, n);
    int s = 0;
    int hi4 = lo + ((hi - lo) & ~3);
    for (int i = lo; i < hi4; i += 4) {
        int4 v = *(const int4*)(g_deg + i);
        s += v.x + v.y + v.z + v.w;
    }
    for (int i = hi4; i < hi; i++) s += g_deg[i];
    sums[t] = s;
    __syncthreads();
    for (int off = 1; off < 1024; off <<= 1) {
        int v = (t >= off) ? sums[t - off] : 0;
        __syncthreads();
        sums[t] += v;
        __syncthreads();
    }
    int run = (t == 0) ? 0 : sums[t - 1];
    for (int i = lo; i < hi; i++) {
        int d = g_deg[i];
        g_rowptr[i] = run;
        g_cursor[i] = run;
        run += d;
    }
    if (hi == n && lo < n) g_rowptr[n] = run;
}

__global__ void k_scatter(const int* __restrict__ ei, int E, int n) {
    int e = blockIdx.x * blockDim.x + threadIdx.x;
    if (e >= E) return;
    int src = ei[e];
    int dst = ei[(size_t)E + e];
    if ((unsigned)src >= (unsigned)n || (unsigned)dst >= (unsigned)n) return;
    int pos = atomicAdd(&g_cursor[dst], 1);
    g_csr_src[pos] = src;
}

// ================= global per-head max of alpha_src =================
__global__ void k_gmax(float* __restrict__ out4, int n) {
    __shared__ float red[8][4];
    int i = blockIdx.x * blockDim.x + threadIdx.x;
    int lane = threadIdx.x & 31;
    int wp = threadIdx.x >> 5;
    float4 v = (i < n) ? ((const float4*)g_as)[i]
                       : make_float4(-1e30f, -1e30f, -1e30f, -1e30f);
#pragma unroll
    for (int o = 16; o > 0; o >>= 1) {
        v.x = fmaxf(v.x, __shfl_xor_sync(0xffffffffu, v.x, o));
        v.y = fmaxf(v.y, __shfl_xor_sync(0xffffffffu, v.y, o));
        v.z = fmaxf(v.z, __shfl_xor_sync(0xffffffffu, v.z, o));
        v.w = fmaxf(v.w, __shfl_xor_sync(0xffffffffu, v.w, o));
    }
    if (lane == 0) { red[wp][0] = v.x; red[wp][1] = v.y; red[wp][2] = v.z; red[wp][3] = v.w; }
    __syncthreads();
    if (threadIdx.x < 4) {
        float m = red[0][threadIdx.x];
#pragma unroll
        for (int r = 1; r < 8; r++) m = fmaxf(m, red[r][threadIdx.x]);
        atomicMaxF(&out4[threadIdx.x], m);
    }
}

// ================= GEMM + alpha epilogue =================
__global__ void gemm128(const float* __restrict__ A, const float* __restrict__ W,
                        float* __restrict__ Out,
                        const float* __restrict__ a_s, const float* __restrict__ a_d,
                        int n) {
    __shared__ float xs[64][32];
    __shared__ float ws[32][128];
    int tid = threadIdx.x;
    int tx = tid & 31;
    int ty = tid >> 5;
    int row0 = blockIdx.x * 64;

    float4 acc[8];
#pragma unroll
    for (int r = 0; r < 8; r++) acc[r] = make_float4(0.f, 0.f, 0.f, 0.f);

    for (int kc = 0; kc < 128; kc += 32) {
#pragma unroll
        for (int i = 0; i < 2; i++) {
            int idx = tid + i * 256;
            int r = idx >> 3;
            int kq = idx & 7;
            float4 v = make_float4(0.f, 0.f, 0.f, 0.f);
            if (row0 + r < n)
                v = *(const float4*)(A + (size_t)(row0 + r) * 128 + kc + kq * 4);
            *(float4*)&xs[r][kq * 4] = v;
        }
#pragma unroll
        for (int i = 0; i < 4; i++) {
            int idx = tid + i * 256;
            int k = idx >> 5;
            int cq = idx & 31;
            *(float4*)&ws[k][cq * 4] = *(const float4*)(W + (size_t)(kc + k) * 128 + cq * 4);
        }
        __syncthreads();
#pragma unroll
        for (int k = 0; k < 32; k++) {
            float4 wv = *(float4*)&ws[k][tx * 4];
#pragma unroll
            for (int r = 0; r < 8; r++) {
                float xv = xs[ty * 8 + r][k];
                acc[r].x += xv * wv.x; acc[r].y += xv * wv.y;
                acc[r].z += xv * wv.z; acc[r].w += xv * wv.w;
            }
        }
        __syncthreads();
    }

    float4 av = ((const float4*)a_s)[tx];
    float4 dv = ((const float4*)a_d)[tx];
    int head = tx >> 3;

#pragma unroll
    for (int r = 0; r < 8; r++) {
        int row = row0 + ty * 8 + r;
        if (row < n)
            *(float4*)(Out + (size_t)row * 128 + tx * 4) = acc[r];
        float ps = acc[r].x * av.x + acc[r].y * av.y + acc[r].z * av.z + acc[r].w * av.w;
        float pd = acc[r].x * dv.x + acc[r].y * dv.y + acc[r].z * dv.z + acc[r].w * dv.w;
#pragma unroll
        for (int o = 1; o < 8; o <<= 1) {
            ps += __shfl_xor_sync(0xffffffffu, ps, o);
            pd += __shfl_xor_sync(0xffffffffu, pd, o);
        }
        if ((tx & 7) == 0 && row < n) {
            g_as[(size_t)row * 4 + head] = ps;
            g_ad[(size_t)row * 4 + head] = pd;
        }
    }
}

// ================= aggregate body =================
// Lane layout: sub = lane&7 (edge within 8-group), head = lane>>3.
// Each lane computes exp for ONE (edge, head) pair; broadcast = 2 shuffles/edge.
__device__ __forceinline__ void run_node(const float* __restrict__ b, float* __restrict__ outf,
                                         const float* __restrict__ gmax4,
                                         const float* __restrict__ sfw,
                                         const float* __restrict__ fcb, int n) {
    int w = (blockIdx.x * blockDim.x + threadIdx.x) >> 5;
    if (w >= n) return;
    int lane = threadIdx.x & 31;
    int head = lane >> 3;
    int hbase = lane & 24;   // head * 8
    int sub = lane & 7;

    int beg = g_rowptr[w];
    int end = g_rowptr[w + 1];

    float4 add4 = *(const float4*)(g_ad + (size_t)w * 4);
    float4 asd4 = *(const float4*)(g_as + (size_t)w * 4);
    float4 gm   = *(const float4*)gmax4;

    float adh = head == 0 ? add4.x : head == 1 ? add4.y : head == 2 ? add4.z : add4.w;
    float ash = head == 0 ? asd4.x : head == 1 ? asd4.y : head == 2 ? asd4.z : asd4.w;
    float gmh = head == 0 ? gm.x   : head == 1 ? gm.y   : head == 2 ? gm.z   : gm.w;
    float sh  = lrelu02(gmh + adh);   // per-head shift (>= all incoming logits)

    float den = 0.f;
    float4 acc = make_float4(0.f, 0.f, 0.f, 0.f);

    for (int c = beg; c < end; c += 8) {
        int j = c + sub;
        int sidx = 0;
        float ex1 = 0.f;
        if (j < end) {
            sidx = g_csr_src[j];
            float a = g_as[(size_t)sidx * 4 + head];
            ex1 = __expf(lrelu02(a + adh) - sh);
        }
        den += ex1;
        int cnt = min(8, end - c);
        if (cnt == 8) {
            int   sk[8];
            float ek[8];
#pragma unroll
            for (int u = 0; u < 8; u++) {
                sk[u] = __shfl_sync(0xffffffffu, sidx, hbase + u);
                ek[u] = __shfl_sync(0xffffffffu, ex1,  hbase + u);
            }
            float4 hv[8];
#pragma unroll
            for (int u = 0; u < 8; u++)
                hv[u] = ((const float4*)(g_h + (size_t)sk[u] * 128))[lane];
#pragma unroll
            for (int u = 0; u < 8; u++) {
                acc.x += ek[u] * hv[u].x; acc.y += ek[u] * hv[u].y;
                acc.z += ek[u] * hv[u].z; acc.w += ek[u] * hv[u].w;
            }
        } else {
            for (int u = 0; u < cnt; u++) {
                int   sk = __shfl_sync(0xffffffffu, sidx, hbase + u);
                float ek = __shfl_sync(0xffffffffu, ex1,  hbase + u);
                float4 hv = ((const float4*)(g_h + (size_t)sk * 128))[lane];
                acc.x += ek * hv.x; acc.y += ek * hv.y;
                acc.z += ek * hv.z; acc.w += ek * hv.w;
            }
        }
    }
    // per-head den: reduce across the 8 lanes of this head group
    den += __shfl_xor_sync(0xffffffffu, den, 1);
    den += __shfl_xor_sync(0xffffffffu, den, 2);
    den += __shfl_xor_sync(0xffffffffu, den, 4);

    // self-loop
    float exs = __expf(lrelu02(ash + adh) - sh);
    den += exs;
    float inv = 1.f / (den + 1e-16f);

    float4 hself = ((const float4*)(g_h + (size_t)w * 128))[lane];
    float4 bv = ((const float4*)b)[lane];
    float4 o;
    o.x = (acc.x + exs * hself.x) * inv + bv.x;
    o.y = (acc.y + exs * hself.y) * inv + bv.y;
    o.z = (acc.z + exs * hself.z) * inv + bv.z;
    o.w = (acc.w + exs * hself.w) * inv + bv.w;
    o.x = o.x > 0.f ? o.x : expm1f(o.x);
    o.y = o.y > 0.f ? o.y : expm1f(o.y);
    o.z = o.z > 0.f ? o.z : expm1f(o.z);
    o.w = o.w > 0.f ? o.w : expm1f(o.w);

    if (sfw == nullptr) {
        ((float4*)(outf + (size_t)w * 128))[lane] = o;
    } else {
        // fused FC: out[w, lane] = fcb[lane] + sum_k feat[k] * fc_w[k, lane]
        float fa = fcb[lane];
#pragma unroll 8
        for (int r = 0; r < 32; r++) {
            float fx = __shfl_sync(0xffffffffu, o.x, r);
            float fy = __shfl_sync(0xffffffffu, o.y, r);
            float fz = __shfl_sync(0xffffffffu, o.z, r);
            float fw2 = __shfl_sync(0xffffffffu, o.w, r);
            int kb = r * 4;
            fa += fx * sfw[kb * 32 + lane] + fy * sfw[(kb + 1) * 32 + lane]
                + fz * sfw[(kb + 2) * 32 + lane] + fw2 * sfw[(kb + 3) * 32 + lane];
        }
        outf[(size_t)w * 32 + lane] = fa;
    }
}

// ================= fused GAT aggregation (warp per dst node) =================
template <bool FUSE>
__global__ void gat_aggregate(const float* __restrict__ b, float* __restrict__ outf,
                              const float* __restrict__ gmax4,
                              const float* __restrict__ fcw, const float* __restrict__ fcb,
                              int n) {
    if constexpr (FUSE) {
        __shared__ float sfw[HID * 32];
#pragma unroll
        for (int i = 0; i < 4; i++)
            ((float4*)sfw)[threadIdx.x + i * 256] = ((const float4*)fcw)[threadIdx.x + i * 256];
        __syncthreads();
        run_node(b, outf, gmax4, sfw, fcb, n);
    } else {
        run_node(b, outf, gmax4, (const float*)nullptr, fcb, n);
    }
}

// ================= launch =================
extern "C" void kernel_launch(void* const* d_in, const int* in_sizes, int n_in,
                              void* d_out, int out_size) {
    const float* x    = (const float*)d_in[0];
    const int*   ei   = (const int*)d_in[1];
    const float* W1   = (const float*)d_in[2];
    const float* a_s1 = (const float*)d_in[3];
    const float* a_d1 = (const float*)d_in[4];
    const float* b1   = (const float*)d_in[5];
    const float* W2   = (const float*)d_in[6];
    const float* a_s2 = (const float*)d_in[7];
    const float* a_d2 = (const float*)d_in[8];
    const float* b2   = (const float*)d_in[9];
    const float* fc_w = (const float*)d_in[10];
    const float* fc_b = (const float*)d_in[11];
    float* out = (float*)d_out;

    int n = in_sizes[0] / HID;
    int E = in_sizes[1] / 2;

    float *p_h, *p_feat, *p_gmax;
    cudaGetSymbolAddress((void**)&p_h, g_h);
    cudaGetSymbolAddress((void**)&p_feat, g_feat);
    cudaGetSymbolAddress((void**)&p_gmax, g_gmax);

    // persistent secondary stream + fork/join events (resource init, not work caching)
    static cudaStream_t sB = nullptr;
    static cudaEvent_t evF = nullptr, evJ = nullptr;
    if (sB == nullptr) {
        cudaStreamCreateWithFlags(&sB, cudaStreamNonBlocking);
        cudaEventCreateWithFlags(&evF, cudaEventDisableTiming);
        cudaEventCreateWithFlags(&evJ, cudaEventDisableTiming);
    }

    int gemm_grid = (n + 63) / 64;
    int warp_grid = (n * 32 + 255) / 256;
    int edge_grid = (E + 255) / 256;
    int node_grid = (n + 255) / 256;

    // ---- fork: CSR build chain on sB, overlapped with gemm1 ----
    cudaEventRecord(evF, 0);
    cudaStreamWaitEvent(sB, evF, 0);
    k_zero_deg<<<node_grid, 256, 0, sB>>>(n);
    k_count<<<edge_grid, 256, 0, sB>>>(ei, E, n);
    k_scan<<<1, 1024, 0, sB>>>(n);
    k_scatter<<<edge_grid, 256, 0, sB>>>(ei, E, n);
    cudaEventRecord(evJ, sB);

    // ---- layer 1 (gemm overlaps CSR build) ----
    gemm128<<<gemm_grid, 256>>>(x, W1, p_h, a_s1, a_d1, n);
    cudaStreamWaitEvent(0, evJ, 0);   // join: need rowptr/csr + gmax init
    k_gmax<<<node_grid, 256>>>(p_gmax, n);
    gat_aggregate<false><<<warp_grid, 256>>>(b1, p_feat, p_gmax, nullptr, nullptr, n);

    // ---- layer 2 (FC fused into aggregation) ----
    gemm128<<<gemm_grid, 256>>>(p_feat, W2, p_h, a_s2, a_d2, n);
    k_gmax<<<node_grid, 256>>>(p_gmax + 4, n);
    gat_aggregate<true><<<warp_grid, 256>>>(b2, out, p_gmax + 4, fc_w, fc_b, n);
}

// round 7
// speedup vs baseline: 1.4370x; 1.0807x over previous
#include <cuda_runtime.h>
#include <cuda_fp16.h>
#include <cstdint>

#define NMAX 50000
#define EMAX 800000
#define HID 128
#define NHEAD 4

// ---------------- scratch (device globals; allocation-free) ----------------
__device__ float  g_h[(size_t)NMAX * HID];      // projected features (fp32, self-loop path)
__device__ __half g_h16[(size_t)NMAX * HID];    // projected features (fp16, edge-gather path)
__device__ float  g_feat[(size_t)NMAX * HID];   // layer-1 output after ELU
__device__ float  g_as[(size_t)NMAX * NHEAD];   // alpha_src per node/head
__device__ float  g_ad[(size_t)NMAX * NHEAD];   // alpha_dst per node/head
__device__ float  g_gmax[2 * NHEAD];            // global per-head max of alpha_src (2 layers)
__device__ int    g_deg[NMAX];
__device__ int    g_rowptr[NMAX + 1];
__device__ int    g_cursor[NMAX];
__device__ int    g_csr_src[EMAX];

__device__ __forceinline__ float lrelu02(float v) { return v > 0.f ? v : 0.2f * v; }

__device__ __forceinline__ void atomicMaxF(float* a, float v) {
    if (v >= 0.f) atomicMax((int*)a, __float_as_int(v));
    else          atomicMin((unsigned int*)a, __float_as_uint(v));
}

// ================= tiny init (stream 0, before fork) =================
__global__ void k_init_gmax() {
    if (threadIdx.x < 2 * NHEAD) g_gmax[threadIdx.x] = -1e30f;
}

// ================= CSR build (secondary stream) =================
__global__ void k_zero_deg(int n) {
    int i = blockIdx.x * blockDim.x + threadIdx.x;
    if (i < n) g_deg[i] = 0;
}

__global__ void k_count(const int* __restrict__ ei, int E, int n) {
    int e = blockIdx.x * blockDim.x + threadIdx.x;
    if (e >= E) return;
    int dst = ei[(size_t)E + e];
    if ((unsigned)dst < (unsigned)n) atomicAdd(&g_deg[dst], 1);
}

// single-block exclusive scan (1024 threads, chunked, int4-vectorized sums)
__global__ void k_scan(int n) {
    __shared__ int sums[1024];
    int t = threadIdx.x;
    int chunk = (((n + 1023) / 1024) + 3) & ~3;
    int lo = min(t * chunk, n);
    int hi = min(lo + chunk, n);
    int s = 0;
    int hi4 = lo + ((hi - lo) & ~3);
    for (int i = lo; i < hi4; i += 4) {
        int4 v = *(const int4*)(g_deg + i);
        s += v.x + v.y + v.z + v.w;
    }
    for (int i = hi4; i < hi; i++) s += g_deg[i];
    sums[t] = s;
    __syncthreads();
    for (int off = 1; off < 1024; off <<= 1) {
        int v = (t >= off) ? sums[t - off] : 0;
        __syncthreads();
        sums[t] += v;
        __syncthreads();
    }
    int run = (t == 0) ? 0 : sums[t - 1];
    for (int i = lo; i < hi; i++) {
        int d = g_deg[i];
        g_rowptr[i] = run;
        g_cursor[i] = run;
        run += d;
    }
    if (hi == n && lo < n) g_rowptr[n] = run;
}

__global__ void k_scatter(const int* __restrict__ ei, int E, int n) {
    int e = blockIdx.x * blockDim.x + threadIdx.x;
    if (e >= E) return;
    int src = ei[e];
    int dst = ei[(size_t)E + e];
    if ((unsigned)src >= (unsigned)n || (unsigned)dst >= (unsigned)n) return;
    int pos = atomicAdd(&g_cursor[dst], 1);
    g_csr_src[pos] = src;
}

// ================= GEMM + alpha/gmax epilogue =================
__global__ void gemm128(const float* __restrict__ A, const float* __restrict__ W,
                        float* __restrict__ Out, __half* __restrict__ Out16,
                        const float* __restrict__ a_s, const float* __restrict__ a_d,
                        float* __restrict__ gmax4, int n) {
    __shared__ float xs[64][32];
    __shared__ float ws[32][128];
    __shared__ float smax[NHEAD];
    int tid = threadIdx.x;
    int tx = tid & 31;
    int ty = tid >> 5;
    int row0 = blockIdx.x * 64;
    if (tid < NHEAD) smax[tid] = -1e30f;

    float4 acc[8];
#pragma unroll
    for (int r = 0; r < 8; r++) acc[r] = make_float4(0.f, 0.f, 0.f, 0.f);

    for (int kc = 0; kc < 128; kc += 32) {
#pragma unroll
        for (int i = 0; i < 2; i++) {
            int idx = tid + i * 256;
            int r = idx >> 3;
            int kq = idx & 7;
            float4 v = make_float4(0.f, 0.f, 0.f, 0.f);
            if (row0 + r < n)
                v = *(const float4*)(A + (size_t)(row0 + r) * 128 + kc + kq * 4);
            *(float4*)&xs[r][kq * 4] = v;
        }
#pragma unroll
        for (int i = 0; i < 4; i++) {
            int idx = tid + i * 256;
            int k = idx >> 5;
            int cq = idx & 31;
            *(float4*)&ws[k][cq * 4] = *(const float4*)(W + (size_t)(kc + k) * 128 + cq * 4);
        }
        __syncthreads();
#pragma unroll
        for (int k = 0; k < 32; k++) {
            float4 wv = *(float4*)&ws[k][tx * 4];
#pragma unroll
            for (int r = 0; r < 8; r++) {
                float xv = xs[ty * 8 + r][k];
                acc[r].x += xv * wv.x; acc[r].y += xv * wv.y;
                acc[r].z += xv * wv.z; acc[r].w += xv * wv.w;
            }
        }
        __syncthreads();
    }

    float4 av = ((const float4*)a_s)[tx];
    float4 dv = ((const float4*)a_d)[tx];
    int head = tx >> 3;

#pragma unroll
    for (int r = 0; r < 8; r++) {
        int row = row0 + ty * 8 + r;
        if (row < n) {
            *(float4*)(Out + (size_t)row * 128 + tx * 4) = acc[r];
            // fp16 copy for the edge-gather path
            __half2 p0 = __floats2half2_rn(acc[r].x, acc[r].y);
            __half2 p1 = __floats2half2_rn(acc[r].z, acc[r].w);
            uint2 u;
            u.x = *(unsigned int*)&p0;
            u.y = *(unsigned int*)&p1;
            ((uint2*)(Out16 + (size_t)row * 128))[tx] = u;
        }
        float ps = acc[r].x * av.x + acc[r].y * av.y + acc[r].z * av.z + acc[r].w * av.w;
        float pd = acc[r].x * dv.x + acc[r].y * dv.y + acc[r].z * dv.z + acc[r].w * dv.w;
#pragma unroll
        for (int o = 1; o < 8; o <<= 1) {
            ps += __shfl_xor_sync(0xffffffffu, ps, o);
            pd += __shfl_xor_sync(0xffffffffu, pd, o);
        }
        if ((tx & 7) == 0 && row < n) {
            g_as[(size_t)row * 4 + head] = ps;
            g_ad[(size_t)row * 4 + head] = pd;
            atomicMaxF(&smax[head], ps);     // block-level max of alpha_src
        }
    }
    __syncthreads();
    if (tid < NHEAD) atomicMaxF(&gmax4[tid], smax[tid]);
}

// ================= aggregate body =================
// Lane layout: sub = lane&7 (edge within 8-group), head = lane>>3.
__device__ __forceinline__ void run_node(const float* __restrict__ b, float* __restrict__ outf,
                                         const float* __restrict__ gmax4,
                                         const float* __restrict__ sfw,
                                         const float* __restrict__ fcb, int n) {
    int w = (blockIdx.x * blockDim.x + threadIdx.x) >> 5;
    if (w >= n) return;
    int lane = threadIdx.x & 31;
    int head = lane >> 3;
    int hbase = lane & 24;
    int sub = lane & 7;

    int beg = g_rowptr[w];
    int end = g_rowptr[w + 1];

    float4 add4 = *(const float4*)(g_ad + (size_t)w * 4);
    float4 asd4 = *(const float4*)(g_as + (size_t)w * 4);
    float4 gm   = *(const float4*)gmax4;

    float adh = head == 0 ? add4.x : head == 1 ? add4.y : head == 2 ? add4.z : add4.w;
    float ash = head == 0 ? asd4.x : head == 1 ? asd4.y : head == 2 ? asd4.z : asd4.w;
    float gmh = head == 0 ? gm.x   : head == 1 ? gm.y   : head == 2 ? gm.z   : gm.w;
    float sh  = lrelu02(gmh + adh);   // per-head shift (>= all incoming logits)

    float den = 0.f;
    float4 acc = make_float4(0.f, 0.f, 0.f, 0.f);

    for (int c = beg; c < end; c += 8) {
        int j = c + sub;
        int sidx = 0;
        float ex1 = 0.f;
        if (j < end) {
            sidx = g_csr_src[j];
            float a = g_as[(size_t)sidx * 4 + head];
            ex1 = __expf(lrelu02(a + adh) - sh);
        }
        den += ex1;
        int cnt = min(8, end - c);
        if (cnt == 8) {
            int   sk[8];
            float ek[8];
#pragma unroll
            for (int u = 0; u < 8; u++) {
                sk[u] = __shfl_sync(0xffffffffu, sidx, hbase + u);
                ek[u] = __shfl_sync(0xffffffffu, ex1,  hbase + u);
            }
            uint2 hv[8];
#pragma unroll
            for (int u = 0; u < 8; u++)
                hv[u] = ((const uint2*)(g_h16 + (size_t)sk[u] * 128))[lane];
#pragma unroll
            for (int u = 0; u < 8; u++) {
                float2 f0 = __half22float2(*(__half2*)&hv[u].x);
                float2 f1 = __half22float2(*(__half2*)&hv[u].y);
                acc.x += ek[u] * f0.x; acc.y += ek[u] * f0.y;
                acc.z += ek[u] * f1.x; acc.w += ek[u] * f1.y;
            }
        } else {
            for (int u = 0; u < cnt; u++) {
                int   sk = __shfl_sync(0xffffffffu, sidx, hbase + u);
                float ek = __shfl_sync(0xffffffffu, ex1,  hbase + u);
                uint2 hu = ((const uint2*)(g_h16 + (size_t)sk * 128))[lane];
                float2 f0 = __half22float2(*(__half2*)&hu.x);
                float2 f1 = __half22float2(*(__half2*)&hu.y);
                acc.x += ek * f0.x; acc.y += ek * f0.y;
                acc.z += ek * f1.x; acc.w += ek * f1.y;
            }
        }
    }
    // per-head den: reduce across the 8 lanes of this head group
    den += __shfl_xor_sync(0xffffffffu, den, 1);
    den += __shfl_xor_sync(0xffffffffu, den, 2);
    den += __shfl_xor_sync(0xffffffffu, den, 4);

    // self-loop (exact fp32 path)
    float exs = __expf(lrelu02(ash + adh) - sh);
    den += exs;
    float inv = 1.f / (den + 1e-16f);

    float4 hself = ((const float4*)(g_h + (size_t)w * 128))[lane];
    float4 bv = ((const float4*)b)[lane];
    float4 o;
    o.x = (acc.x + exs * hself.x) * inv + bv.x;
    o.y = (acc.y + exs * hself.y) * inv + bv.y;
    o.z = (acc.z + exs * hself.z) * inv + bv.z;
    o.w = (acc.w + exs * hself.w) * inv + bv.w;
    o.x = o.x > 0.f ? o.x : expm1f(o.x);
    o.y = o.y > 0.f ? o.y : expm1f(o.y);
    o.z = o.z > 0.f ? o.z : expm1f(o.z);
    o.w = o.w > 0.f ? o.w : expm1f(o.w);

    if (sfw == nullptr) {
        ((float4*)(outf + (size_t)w * 128))[lane] = o;
    } else {
        float fa = fcb[lane];
#pragma unroll 8
        for (int r = 0; r < 32; r++) {
            float fx = __shfl_sync(0xffffffffu, o.x, r);
            float fy = __shfl_sync(0xffffffffu, o.y, r);
            float fz = __shfl_sync(0xffffffffu, o.z, r);
            float fw2 = __shfl_sync(0xffffffffu, o.w, r);
            int kb = r * 4;
            fa += fx * sfw[kb * 32 + lane] + fy * sfw[(kb + 1) * 32 + lane]
                + fz * sfw[(kb + 2) * 32 + lane] + fw2 * sfw[(kb + 3) * 32 + lane];
        }
        outf[(size_t)w * 32 + lane] = fa;
    }
}

// ================= fused GAT aggregation (warp per dst node) =================
template <bool FUSE>
__global__ void gat_aggregate(const float* __restrict__ b, float* __restrict__ outf,
                              const float* __restrict__ gmax4,
                              const float* __restrict__ fcw, const float* __restrict__ fcb,
                              int n) {
    if constexpr (FUSE) {
        __shared__ float sfw[HID * 32];
#pragma unroll
        for (int i = 0; i < 4; i++)
            ((float4*)sfw)[threadIdx.x + i * 256] = ((const float4*)fcw)[threadIdx.x + i * 256];
        __syncthreads();
        run_node(b, outf, gmax4, sfw, fcb, n);
    } else {
        run_node(b, outf, gmax4, (const float*)nullptr, fcb, n);
    }
}

// ================= launch =================
extern "C" void kernel_launch(void* const* d_in, const int* in_sizes, int n_in,
                              void* d_out, int out_size) {
    const float* x    = (const float*)d_in[0];
    const int*   ei   = (const int*)d_in[1];
    const float* W1   = (const float*)d_in[2];
    const float* a_s1 = (const float*)d_in[3];
    const float* a_d1 = (const float*)d_in[4];
    const float* b1   = (const float*)d_in[5];
    const float* W2   = (const float*)d_in[6];
    const float* a_s2 = (const float*)d_in[7];
    const float* a_d2 = (const float*)d_in[8];
    const float* b2   = (const float*)d_in[9];
    const float* fc_w = (const float*)d_in[10];
    const float* fc_b = (const float*)d_in[11];
    float* out = (float*)d_out;

    int n = in_sizes[0] / HID;
    int E = in_sizes[1] / 2;

    float *p_h, *p_feat, *p_gmax;
    __half* p_h16;
    cudaGetSymbolAddress((void**)&p_h, g_h);
    cudaGetSymbolAddress((void**)&p_h16, g_h16);
    cudaGetSymbolAddress((void**)&p_feat, g_feat);
    cudaGetSymbolAddress((void**)&p_gmax, g_gmax);

    static cudaStream_t sB = nullptr;
    static cudaEvent_t evF = nullptr, evJ = nullptr;
    if (sB == nullptr) {
        cudaStreamCreateWithFlags(&sB, cudaStreamNonBlocking);
        cudaEventCreateWithFlags(&evF, cudaEventDisableTiming);
        cudaEventCreateWithFlags(&evJ, cudaEventDisableTiming);
    }

    int gemm_grid = (n + 63) / 64;
    int warp_grid = (n * 32 + 255) / 256;
    int edge_grid = (E + 255) / 256;
    int node_grid = (n + 255) / 256;

    // gmax init on stream 0 BEFORE the fork so gemm1's atomics are ordered after it
    k_init_gmax<<<1, 32>>>();

    // ---- fork: CSR build chain on sB, overlapped with gemm1 ----
    cudaEventRecord(evF, 0);
    cudaStreamWaitEvent(sB, evF, 0);
    k_zero_deg<<<node_grid, 256, 0, sB>>>(n);
    k_count<<<edge_grid, 256, 0, sB>>>(ei, E, n);
    k_scan<<<1, 1024, 0, sB>>>(n);
    k_scatter<<<edge_grid, 256, 0, sB>>>(ei, E, n);
    cudaEventRecord(evJ, sB);

    // ---- layer 1 (gemm overlaps CSR build; gmax fused into epilogue) ----
    gemm128<<<gemm_grid, 256>>>(x, W1, p_h, p_h16, a_s1, a_d1, p_gmax, n);
    cudaStreamWaitEvent(0, evJ, 0);
    gat_aggregate<false><<<warp_grid, 256>>>(b1, p_feat, p_gmax, nullptr, nullptr, n);

    // ---- layer 2 (FC fused into aggregation) ----
    gemm128<<<gemm_grid, 256>>>(p_feat, W2, p_h, p_h16, a_s2, a_d2, p_gmax + 4, n);
    gat_aggregate<true><<<warp_grid, 256>>>(b2, out, p_gmax + 4, fc_w, fc_b, n);
}

// round 8
// speedup vs baseline: 1.8160x; 1.2637x over previous
#include <cuda_runtime.h>
#include <cuda_fp16.h>
#include <cstdint>

#define NMAX 50000
#define EMAX 800000
#define HID 128
#define NHEAD 4
#define SCAN_BLK 1024                      // elements per scan block
#define SCAN_NB ((NMAX + SCAN_BLK - 1) / SCAN_BLK)

// ---------------- scratch (device globals; allocation-free) ----------------
__device__ float  g_h[(size_t)NMAX * HID];      // projected features (fp32, self-loop path)
__device__ __half g_h16[(size_t)NMAX * HID];    // projected features (fp16, edge-gather path)
__device__ float  g_feat[(size_t)NMAX * HID];   // layer-1 output after ELU
__device__ float  g_as[(size_t)NMAX * NHEAD];   // alpha_src per node/head
__device__ float  g_ad[(size_t)NMAX * NHEAD];   // alpha_dst per node/head
__device__ float  g_gmax[2 * NHEAD];            // global per-head max of alpha_src (2 layers)
__device__ int    g_deg[NMAX];
__device__ int    g_rowptr[NMAX + 1];
__device__ int    g_cursor[NMAX];
__device__ int    g_csr_src[EMAX];
__device__ int    g_bsum[SCAN_NB];              // per-block degree sums
__device__ int    g_boff[SCAN_NB];              // per-block exclusive offsets

__device__ __forceinline__ float lrelu02(float v) { return v > 0.f ? v : 0.2f * v; }

__device__ __forceinline__ void atomicMaxF(float* a, float v) {
    if (v >= 0.f) atomicMax((int*)a, __float_as_int(v));
    else          atomicMin((unsigned int*)a, __float_as_uint(v));
}

// ================= tiny init (stream 0, before fork) =================
__global__ void k_init_gmax() {
    if (threadIdx.x < 2 * NHEAD) g_gmax[threadIdx.x] = -1e30f;
}

// ================= CSR build (secondary stream) =================
__global__ void k_zero_deg(int n) {
    int i = blockIdx.x * blockDim.x + threadIdx.x;
    if (i < n) g_deg[i] = 0;
}

__global__ void k_count(const int* __restrict__ ei, int E, int n) {
    int e = blockIdx.x * blockDim.x + threadIdx.x;
    if (e >= E) return;
    int dst = ei[(size_t)E + e];
    if ((unsigned)dst < (unsigned)n) atomicAdd(&g_deg[dst], 1);
}

// ---- scan phase A: per-block reduce (256 thr x 4 elems) ----
__global__ void k_scan_a(int n) {
    __shared__ int wsum[8];
    int base = blockIdx.x * SCAN_BLK + threadIdx.x * 4;
    int s = 0;
    if (base + 3 < n) {
        int4 v = *(const int4*)(g_deg + base);
        s = v.x + v.y + v.z + v.w;
    } else {
        for (int i = 0; i < 4; i++) if (base + i < n) s += g_deg[base + i];
    }
#pragma unroll
    for (int o = 16; o > 0; o >>= 1) s += __shfl_xor_sync(0xffffffffu, s, o);
    if ((threadIdx.x & 31) == 0) wsum[threadIdx.x >> 5] = s;
    __syncthreads();
    if (threadIdx.x == 0) {
        int t = 0;
#pragma unroll
        for (int i = 0; i < 8; i++) t += wsum[i];
        g_bsum[blockIdx.x] = t;
    }
}

// ---- scan phase B: exclusive scan of block sums (single tiny block) ----
__global__ void k_scan_b(int nb, int n) {
    if (threadIdx.x == 0) {
        int run = 0;
        for (int i = 0; i < nb; i++) {
            g_boff[i] = run;
            run += g_bsum[i];
        }
        g_rowptr[n] = run;
    }
}

// ---- scan phase C: intra-block exclusive scan + offset, write rowptr/cursor ----
__global__ void k_scan_c(int n) {
    __shared__ int woff[8];
    int tid = threadIdx.x;
    int base = blockIdx.x * SCAN_BLK + tid * 4;

    int d0 = 0, d1 = 0, d2 = 0, d3 = 0;
    if (base + 3 < n) {
        int4 v = *(const int4*)(g_deg + base);
        d0 = v.x; d1 = v.y; d2 = v.z; d3 = v.w;
    } else {
        if (base + 0 < n) d0 = g_deg[base + 0];
        if (base + 1 < n) d1 = g_deg[base + 1];
        if (base + 2 < n) d2 = g_deg[base + 2];
        if (base + 3 < n) d3 = g_deg[base + 3];
    }
    int ts = d0 + d1 + d2 + d3;

    // inclusive warp scan of thread sums
    int inc = ts;
#pragma unroll
    for (int o = 1; o < 32; o <<= 1) {
        int v = __shfl_up_sync(0xffffffffu, inc, o);
        if ((tid & 31) >= o) inc += v;
    }
    if ((tid & 31) == 31) woff[tid >> 5] = inc;
    __syncthreads();
    if (tid < 8) {
        int v = woff[tid];
        int e = 0;
        for (int i = 0; i < 8; i++) { int u = __shfl_sync(0xffu, v, i, 8); if (i < tid) e += u; }
        woff[tid] = e;
    }
    __syncthreads();
    int excl = inc - ts + woff[tid >> 5] + g_boff[blockIdx.x];

    int p0 = excl, p1 = p0 + d0, p2 = p1 + d1, p3 = p2 + d2;
    if (base + 3 < n) {
        int4 pv = make_int4(p0, p1, p2, p3);
        *(int4*)(g_rowptr + base) = pv;
        *(int4*)(g_cursor + base) = pv;
    } else {
        if (base + 0 < n) { g_rowptr[base + 0] = p0; g_cursor[base + 0] = p0; }
        if (base + 1 < n) { g_rowptr[base + 1] = p1; g_cursor[base + 1] = p1; }
        if (base + 2 < n) { g_rowptr[base + 2] = p2; g_cursor[base + 2] = p2; }
        if (base + 3 < n) { g_rowptr[base + 3] = p3; g_cursor[base + 3] = p3; }
    }
}

__global__ void k_scatter(const int* __restrict__ ei, int E, int n) {
    int e = blockIdx.x * blockDim.x + threadIdx.x;
    if (e >= E) return;
    int src = ei[e];
    int dst = ei[(size_t)E + e];
    if ((unsigned)src >= (unsigned)n || (unsigned)dst >= (unsigned)n) return;
    int pos = atomicAdd(&g_cursor[dst], 1);
    g_csr_src[pos] = src;
}

// ================= GEMM + alpha/gmax epilogue =================
__global__ void gemm128(const float* __restrict__ A, const float* __restrict__ W,
                        float* __restrict__ Out, __half* __restrict__ Out16,
                        const float* __restrict__ a_s, const float* __restrict__ a_d,
                        float* __restrict__ gmax4, int n) {
    __shared__ float xs[64][32];
    __shared__ float ws[32][128];
    __shared__ float smax[NHEAD];
    int tid = threadIdx.x;
    int tx = tid & 31;
    int ty = tid >> 5;
    int row0 = blockIdx.x * 64;
    if (tid < NHEAD) smax[tid] = -1e30f;

    float4 acc[8];
#pragma unroll
    for (int r = 0; r < 8; r++) acc[r] = make_float4(0.f, 0.f, 0.f, 0.f);

    for (int kc = 0; kc < 128; kc += 32) {
#pragma unroll
        for (int i = 0; i < 2; i++) {
            int idx = tid + i * 256;
            int r = idx >> 3;
            int kq = idx & 7;
            float4 v = make_float4(0.f, 0.f, 0.f, 0.f);
            if (row0 + r < n)
                v = *(const float4*)(A + (size_t)(row0 + r) * 128 + kc + kq * 4);
            *(float4*)&xs[r][kq * 4] = v;
        }
#pragma unroll
        for (int i = 0; i < 4; i++) {
            int idx = tid + i * 256;
            int k = idx >> 5;
            int cq = idx & 31;
            *(float4*)&ws[k][cq * 4] = *(const float4*)(W + (size_t)(kc + k) * 128 + cq * 4);
        }
        __syncthreads();
#pragma unroll
        for (int k = 0; k < 32; k++) {
            float4 wv = *(float4*)&ws[k][tx * 4];
#pragma unroll
            for (int r = 0; r < 8; r++) {
                float xv = xs[ty * 8 + r][k];
                acc[r].x += xv * wv.x; acc[r].y += xv * wv.y;
                acc[r].z += xv * wv.z; acc[r].w += xv * wv.w;
            }
        }
        __syncthreads();
    }

    float4 av = ((const float4*)a_s)[tx];
    float4 dv = ((const float4*)a_d)[tx];
    int head = tx >> 3;

#pragma unroll
    for (int r = 0; r < 8; r++) {
        int row = row0 + ty * 8 + r;
        if (row < n) {
            *(float4*)(Out + (size_t)row * 128 + tx * 4) = acc[r];
            __half2 p0 = __floats2half2_rn(acc[r].x, acc[r].y);
            __half2 p1 = __floats2half2_rn(acc[r].z, acc[r].w);
            uint2 u;
            u.x = *(unsigned int*)&p0;
            u.y = *(unsigned int*)&p1;
            ((uint2*)(Out16 + (size_t)row * 128))[tx] = u;
        }
        float ps = acc[r].x * av.x + acc[r].y * av.y + acc[r].z * av.z + acc[r].w * av.w;
        float pd = acc[r].x * dv.x + acc[r].y * dv.y + acc[r].z * dv.z + acc[r].w * dv.w;
#pragma unroll
        for (int o = 1; o < 8; o <<= 1) {
            ps += __shfl_xor_sync(0xffffffffu, ps, o);
            pd += __shfl_xor_sync(0xffffffffu, pd, o);
        }
        if ((tx & 7) == 0 && row < n) {
            g_as[(size_t)row * 4 + head] = ps;
            g_ad[(size_t)row * 4 + head] = pd;
            atomicMaxF(&smax[head], ps);
        }
    }
    __syncthreads();
    if (tid < NHEAD) atomicMaxF(&gmax4[tid], smax[tid]);
}

// ================= aggregate body =================
__device__ __forceinline__ void run_node(const float* __restrict__ b, float* __restrict__ outf,
                                         const float* __restrict__ gmax4,
                                         const float* __restrict__ sfw,
                                         const float* __restrict__ fcb, int n) {
    int w = (blockIdx.x * blockDim.x + threadIdx.x) >> 5;
    if (w >= n) return;
    int lane = threadIdx.x & 31;
    int head = lane >> 3;
    int hbase = lane & 24;
    int sub = lane & 7;

    int beg = g_rowptr[w];
    int end = g_rowptr[w + 1];

    float4 add4 = *(const float4*)(g_ad + (size_t)w * 4);
    float4 asd4 = *(const float4*)(g_as + (size_t)w * 4);
    float4 gm   = *(const float4*)gmax4;

    float adh = head == 0 ? add4.x : head == 1 ? add4.y : head == 2 ? add4.z : add4.w;
    float ash = head == 0 ? asd4.x : head == 1 ? asd4.y : head == 2 ? asd4.z : asd4.w;
    float gmh = head == 0 ? gm.x   : head == 1 ? gm.y   : head == 2 ? gm.z   : gm.w;
    float sh  = lrelu02(gmh + adh);

    float den = 0.f;
    float4 acc = make_float4(0.f, 0.f, 0.f, 0.f);

    for (int c = beg; c < end; c += 8) {
        int j = c + sub;
        int sidx = 0;
        float ex1 = 0.f;
        if (j < end) {
            sidx = g_csr_src[j];
            float a = g_as[(size_t)sidx * 4 + head];
            ex1 = __expf(lrelu02(a + adh) - sh);
        }
        den += ex1;
        int cnt = min(8, end - c);
        if (cnt == 8) {
            int   sk[8];
            float ek[8];
#pragma unroll
            for (int u = 0; u < 8; u++) {
                sk[u] = __shfl_sync(0xffffffffu, sidx, hbase + u);
                ek[u] = __shfl_sync(0xffffffffu, ex1,  hbase + u);
            }
            uint2 hv[8];
#pragma unroll
            for (int u = 0; u < 8; u++)
                hv[u] = ((const uint2*)(g_h16 + (size_t)sk[u] * 128))[lane];
#pragma unroll
            for (int u = 0; u < 8; u++) {
                float2 f0 = __half22float2(*(__half2*)&hv[u].x);
                float2 f1 = __half22float2(*(__half2*)&hv[u].y);
                acc.x += ek[u] * f0.x; acc.y += ek[u] * f0.y;
                acc.z += ek[u] * f1.x; acc.w += ek[u] * f1.y;
            }
        } else {
            for (int u = 0; u < cnt; u++) {
                int   sk = __shfl_sync(0xffffffffu, sidx, hbase + u);
                float ek = __shfl_sync(0xffffffffu, ex1,  hbase + u);
                uint2 hu = ((const uint2*)(g_h16 + (size_t)sk * 128))[lane];
                float2 f0 = __half22float2(*(__half2*)&hu.x);
                float2 f1 = __half22float2(*(__half2*)&hu.y);
                acc.x += ek * f0.x; acc.y += ek * f0.y;
                acc.z += ek * f1.x; acc.w += ek * f1.y;
            }
        }
    }
    den += __shfl_xor_sync(0xffffffffu, den, 1);
    den += __shfl_xor_sync(0xffffffffu, den, 2);
    den += __shfl_xor_sync(0xffffffffu, den, 4);

    float exs = __expf(lrelu02(ash + adh) - sh);
    den += exs;
    float inv = 1.f / (den + 1e-16f);

    float4 hself = ((const float4*)(g_h + (size_t)w * 128))[lane];
    float4 bv = ((const float4*)b)[lane];
    float4 o;
    o.x = (acc.x + exs * hself.x) * inv + bv.x;
    o.y = (acc.y + exs * hself.y) * inv + bv.y;
    o.z = (acc.z + exs * hself.z) * inv + bv.z;
    o.w = (acc.w + exs * hself.w) * inv + bv.w;
    o.x = o.x > 0.f ? o.x : expm1f(o.x);
    o.y = o.y > 0.f ? o.y : expm1f(o.y);
    o.z = o.z > 0.f ? o.z : expm1f(o.z);
    o.w = o.w > 0.f ? o.w : expm1f(o.w);

    if (sfw == nullptr) {
        ((float4*)(outf + (size_t)w * 128))[lane] = o;
    } else {
        float fa = fcb[lane];
#pragma unroll 8
        for (int r = 0; r < 32; r++) {
            float fx = __shfl_sync(0xffffffffu, o.x, r);
            float fy = __shfl_sync(0xffffffffu, o.y, r);
            float fz = __shfl_sync(0xffffffffu, o.z, r);
            float fw2 = __shfl_sync(0xffffffffu, o.w, r);
            int kb = r * 4;
            fa += fx * sfw[kb * 32 + lane] + fy * sfw[(kb + 1) * 32 + lane]
                + fz * sfw[(kb + 2) * 32 + lane] + fw2 * sfw[(kb + 3) * 32 + lane];
        }
        outf[(size_t)w * 32 + lane] = fa;
    }
}

template <bool FUSE>
__global__ void gat_aggregate(const float* __restrict__ b, float* __restrict__ outf,
                              const float* __restrict__ gmax4,
                              const float* __restrict__ fcw, const float* __restrict__ fcb,
                              int n) {
    if constexpr (FUSE) {
        __shared__ float sfw[HID * 32];
#pragma unroll
        for (int i = 0; i < 4; i++)
            ((float4*)sfw)[threadIdx.x + i * 256] = ((const float4*)fcw)[threadIdx.x + i * 256];
        __syncthreads();
        run_node(b, outf, gmax4, sfw, fcb, n);
    } else {
        run_node(b, outf, gmax4, (const float*)nullptr, fcb, n);
    }
}

// ================= launch =================
extern "C" void kernel_launch(void* const* d_in, const int* in_sizes, int n_in,
                              void* d_out, int out_size) {
    const float* x    = (const float*)d_in[0];
    const int*   ei   = (const int*)d_in[1];
    const float* W1   = (const float*)d_in[2];
    const float* a_s1 = (const float*)d_in[3];
    const float* a_d1 = (const float*)d_in[4];
    const float* b1   = (const float*)d_in[5];
    const float* W2   = (const float*)d_in[6];
    const float* a_s2 = (const float*)d_in[7];
    const float* a_d2 = (const float*)d_in[8];
    const float* b2   = (const float*)d_in[9];
    const float* fc_w = (const float*)d_in[10];
    const float* fc_b = (const float*)d_in[11];
    float* out = (float*)d_out;

    int n = in_sizes[0] / HID;
    int E = in_sizes[1] / 2;

    float *p_h, *p_feat, *p_gmax;
    __half* p_h16;
    cudaGetSymbolAddress((void**)&p_h, g_h);
    cudaGetSymbolAddress((void**)&p_h16, g_h16);
    cudaGetSymbolAddress((void**)&p_feat, g_feat);
    cudaGetSymbolAddress((void**)&p_gmax, g_gmax);

    static cudaStream_t sB = nullptr;
    static cudaEvent_t evF = nullptr, evJ = nullptr;
    if (sB == nullptr) {
        cudaStreamCreateWithFlags(&sB, cudaStreamNonBlocking);
        cudaEventCreateWithFlags(&evF, cudaEventDisableTiming);
        cudaEventCreateWithFlags(&evJ, cudaEventDisableTiming);
    }

    int gemm_grid = (n + 63) / 64;
    int warp_grid = (n * 32 + 255) / 256;
    int edge_grid = (E + 255) / 256;
    int node_grid = (n + 255) / 256;
    int scan_nb   = (n + SCAN_BLK - 1) / SCAN_BLK;

    k_init_gmax<<<1, 32>>>();

    // ---- fork: CSR build chain on sB, overlapped with gemm1 ----
    cudaEventRecord(evF, 0);
    cudaStreamWaitEvent(sB, evF, 0);
    k_zero_deg<<<node_grid, 256, 0, sB>>>(n);
    k_count<<<edge_grid, 256, 0, sB>>>(ei, E, n);
    k_scan_a<<<scan_nb, 256, 0, sB>>>(n);
    k_scan_b<<<1, 32, 0, sB>>>(scan_nb, n);
    k_scan_c<<<scan_nb, 256, 0, sB>>>(n);
    k_scatter<<<edge_grid, 256, 0, sB>>>(ei, E, n);
    cudaEventRecord(evJ, sB);

    // ---- layer 1 (gemm overlaps CSR build; gmax fused into epilogue) ----
    gemm128<<<gemm_grid, 256>>>(x, W1, p_h, p_h16, a_s1, a_d1, p_gmax, n);
    cudaStreamWaitEvent(0, evJ, 0);
    gat_aggregate<false><<<warp_grid, 256>>>(b1, p_feat, p_gmax, nullptr, nullptr, n);

    // ---- layer 2 (FC fused into aggregation) ----
    gemm128<<<gemm_grid, 256>>>(p_feat, W2, p_h, p_h16, a_s2, a_d2, p_gmax + 4, n);
    gat_aggregate<true><<<warp_grid, 256>>>(b2, out, p_gmax + 4, fc_w, fc_b, n);
}

// round 11
// speedup vs baseline: 2.1415x; 1.1792x over previous
#include <cuda_runtime.h>
#include <cuda_fp16.h>
#include <cstdint>

#define NMAX 50000
#define EMAX 800000
#define HID 128
#define NHEAD 4
#define SCAN_BLK 1024
#define SCAN_NB ((NMAX + SCAN_BLK - 1) / SCAN_BLK)

// ---------------- scratch (device globals; allocation-free) ----------------
__device__ float  g_h[(size_t)NMAX * HID];
__device__ __half g_h16[(size_t)NMAX * HID];
__device__ float  g_feat[(size_t)NMAX * HID];
__device__ float  g_as[(size_t)NMAX * NHEAD];
__device__ float  g_ad[(size_t)NMAX * NHEAD];
__device__ float  g_gmax[2 * NHEAD];
__device__ int    g_deg[NMAX];
__device__ int    g_rowptr[NMAX + 1];
__device__ int    g_cursor[NMAX];
__device__ int    g_csr_src[EMAX];
__device__ int    g_bsum[SCAN_NB];
__device__ int    g_boff[SCAN_NB];

__device__ __forceinline__ float lrelu02(float v) { return v > 0.f ? v : 0.2f * v; }

__device__ __forceinline__ void atomicMaxF(float* a, float v) {
    if (v >= 0.f) atomicMax((int*)a, __float_as_int(v));
    else          atomicMin((unsigned int*)a, __float_as_uint(v));
}

__device__ __forceinline__ unsigned f2tf32(float f) {
    unsigned u;
    asm("cvt.rna.tf32.f32 %0, %1;" : "=r"(u) : "f"(f));
    return u;
}

__device__ __forceinline__ void mma_tf32(float* c, unsigned a0, unsigned a1, unsigned a2,
                                         unsigned a3, unsigned b0, unsigned b1) {
    asm volatile(
        "mma.sync.aligned.m16n8k8.row.col.f32.tf32.tf32.f32 "
        "{%0,%1,%2,%3}, {%4,%5,%6,%7}, {%8,%9}, {%0,%1,%2,%3};"
        : "+f"(c[0]), "+f"(c[1]), "+f"(c[2]), "+f"(c[3])
        : "r"(a0), "r"(a1), "r"(a2), "r"(a3), "r"(b0), "r"(b1));
}

// ================= tiny init =================
__global__ void k_init_gmax() {
    if (threadIdx.x < 2 * NHEAD) g_gmax[threadIdx.x] = -1e30f;
}

// ================= CSR build (secondary stream) =================
__global__ void k_zero_deg(int n) {
    int i = blockIdx.x * blockDim.x + threadIdx.x;
    if (i < n) g_deg[i] = 0;
}

__global__ void k_count(const int* __restrict__ ei, int E, int n) {
    int e = blockIdx.x * blockDim.x + threadIdx.x;
    if (e >= E) return;
    int dst = ei[(size_t)E + e];
    if ((unsigned)dst < (unsigned)n) atomicAdd(&g_deg[dst], 1);
}

__global__ void k_scan_a(int n) {
    __shared__ int wsum[8];
    int base = blockIdx.x * SCAN_BLK + threadIdx.x * 4;
    int s = 0;
    if (base + 3 < n) {
        int4 v = *(const int4*)(g_deg + base);
        s = v.x + v.y + v.z + v.w;
    } else {
        for (int i = 0; i < 4; i++) if (base + i < n) s += g_deg[base + i];
    }
#pragma unroll
    for (int o = 16; o > 0; o >>= 1) s += __shfl_xor_sync(0xffffffffu, s, o);
    if ((threadIdx.x & 31) == 0) wsum[threadIdx.x >> 5] = s;
    __syncthreads();
    if (threadIdx.x == 0) {
        int t = 0;
#pragma unroll
        for (int i = 0; i < 8; i++) t += wsum[i];
        g_bsum[blockIdx.x] = t;
    }
}

__global__ void k_scan_b(int nb, int n) {
    if (threadIdx.x == 0) {
        int run = 0;
        for (int i = 0; i < nb; i++) {
            g_boff[i] = run;
            run += g_bsum[i];
        }
        g_rowptr[n] = run;
    }
}

__global__ void k_scan_c(int n) {
    __shared__ int woff[8];
    int tid = threadIdx.x;
    int base = blockIdx.x * SCAN_BLK + tid * 4;

    int d0 = 0, d1 = 0, d2 = 0, d3 = 0;
    if (base + 3 < n) {
        int4 v = *(const int4*)(g_deg + base);
        d0 = v.x; d1 = v.y; d2 = v.z; d3 = v.w;
    } else {
        if (base + 0 < n) d0 = g_deg[base + 0];
        if (base + 1 < n) d1 = g_deg[base + 1];
        if (base + 2 < n) d2 = g_deg[base + 2];
        if (base + 3 < n) d3 = g_deg[base + 3];
    }
    int ts = d0 + d1 + d2 + d3;

    int inc = ts;
#pragma unroll
    for (int o = 1; o < 32; o <<= 1) {
        int v = __shfl_up_sync(0xffffffffu, inc, o);
        if ((tid & 31) >= o) inc += v;
    }
    if ((tid & 31) == 31) woff[tid >> 5] = inc;
    __syncthreads();
    if (tid < 8) {
        int v = woff[tid];
        int e = 0;
        for (int i = 0; i < 8; i++) { int u = __shfl_sync(0xffu, v, i, 8); if (i < tid) e += u; }
        woff[tid] = e;
    }
    __syncthreads();
    int excl = inc - ts + woff[tid >> 5] + g_boff[blockIdx.x];

    int p0 = excl, p1 = p0 + d0, p2 = p1 + d1, p3 = p2 + d2;
    if (base + 3 < n) {
        int4 pv = make_int4(p0, p1, p2, p3);
        *(int4*)(g_rowptr + base) = pv;
        *(int4*)(g_cursor + base) = pv;
    } else {
        if (base + 0 < n) { g_rowptr[base + 0] = p0; g_cursor[base + 0] = p0; }
        if (base + 1 < n) { g_rowptr[base + 1] = p1; g_cursor[base + 1] = p1; }
        if (base + 2 < n) { g_rowptr[base + 2] = p2; g_cursor[base + 2] = p2; }
        if (base + 3 < n) { g_rowptr[base + 3] = p3; g_cursor[base + 3] = p3; }
    }
}

__global__ void k_scatter(const int* __restrict__ ei, int E, int n) {
    int e = blockIdx.x * blockDim.x + threadIdx.x;
    if (e >= E) return;
    int src = ei[e];
    int dst = ei[(size_t)E + e];
    if ((unsigned)src >= (unsigned)n || (unsigned)dst >= (unsigned)n) return;
    int pos = atomicAdd(&g_cursor[dst], 1);
    g_csr_src[pos] = src;
}

// ================= tf32 tensor-core GEMM + alpha/gmax epilogue =================
// Block: 64 rows x 128 cols, 8 warps, each warp a 16x64 tile via m16n8k8.
__global__ void gemm128_tc(const float* __restrict__ A, const float* __restrict__ W,
                           float* __restrict__ Out, __half* __restrict__ Out16,
                           const float* __restrict__ a_s, const float* __restrict__ a_d,
                           float* __restrict__ gmax4, int n) {
    __shared__ unsigned xs[64 * 36];    // padded stride 36 (bank-conflict-free)
    __shared__ unsigned ws[32 * 136];   // padded stride 136
    __shared__ float smax[NHEAD];
    int tid = threadIdx.x;
    int lane = tid & 31;
    int wid = tid >> 5;
    int gid = lane >> 2;   // quad id: row within mma tile
    int tig = lane & 3;    // thread in quad: col pair
    int rw = wid >> 1;     // warp row tile (0..3) -> rows rw*16..+16
    int cw = wid & 1;      // warp col tile (0..1) -> cols cw*64..+64
    int row0 = blockIdx.x * 64;
    if (tid < NHEAD) smax[tid] = -1e30f;

    float acc[8][4];
#pragma unroll
    for (int nt = 0; nt < 8; nt++)
#pragma unroll
        for (int q = 0; q < 4; q++) acc[nt][q] = 0.f;

    for (int kc = 0; kc < 128; kc += 32) {
        // stage A chunk (64x32) with tf32 rounding
#pragma unroll
        for (int i = 0; i < 2; i++) {
            int idx = tid + i * 256;
            int r = idx >> 3;
            int kq = idx & 7;
            float4 v = make_float4(0.f, 0.f, 0.f, 0.f);
            if (row0 + r < n)
                v = *(const float4*)(A + (size_t)(row0 + r) * 128 + kc + kq * 4);
            uint4 u = make_uint4(f2tf32(v.x), f2tf32(v.y), f2tf32(v.z), f2tf32(v.w));
            *(uint4*)&xs[r * 36 + kq * 4] = u;
        }
        // stage W chunk (32x128) with tf32 rounding
#pragma unroll
        for (int i = 0; i < 4; i++) {
            int idx = tid + i * 256;
            int k = idx >> 5;
            int cq = idx & 31;
            float4 v = *(const float4*)(W + (size_t)(kc + k) * 128 + cq * 4);
            uint4 u = make_uint4(f2tf32(v.x), f2tf32(v.y), f2tf32(v.z), f2tf32(v.w));
            *(uint4*)&ws[k * 136 + cq * 4] = u;
        }
        __syncthreads();

        int ar0 = (rw * 16 + gid) * 36;
        int ar1 = (rw * 16 + gid + 8) * 36;
        int cb = cw * 64 + gid;
#pragma unroll
        for (int kk = 0; kk < 32; kk += 8) {
            unsigned a0 = xs[ar0 + kk + tig];
            unsigned a1 = xs[ar1 + kk + tig];
            unsigned a2 = xs[ar0 + kk + tig + 4];
            unsigned a3 = xs[ar1 + kk + tig + 4];
            int wr0 = (kk + tig) * 136;
            int wr1 = (kk + tig + 4) * 136;
#pragma unroll
            for (int nt = 0; nt < 8; nt++) {
                unsigned b0 = ws[wr0 + cb + nt * 8];
                unsigned b1 = ws[wr1 + cb + nt * 8];
                mma_tf32(acc[nt], a0, a1, a2, a3, b0, b1);
            }
        }
        __syncthreads();
    }

    // ---- epilogue: store fp32 + fp16, alpha dots, block gmax ----
    int r_lo = row0 + rw * 16 + gid;
    int r_hi = r_lo + 8;
    int hA = 2 * cw, hB = 2 * cw + 1;

    float psA_lo = 0.f, psB_lo = 0.f, pdA_lo = 0.f, pdB_lo = 0.f;
    float psA_hi = 0.f, psB_hi = 0.f, pdA_hi = 0.f, pdB_hi = 0.f;

#pragma unroll
    for (int nt = 0; nt < 8; nt++) {
        int c = cw * 64 + nt * 8 + 2 * tig;
        float as0 = a_s[c], as1 = a_s[c + 1];
        float ad0 = a_d[c], ad1 = a_d[c + 1];
        if (r_lo < n) {
            *(float2*)(Out + (size_t)r_lo * 128 + c) = make_float2(acc[nt][0], acc[nt][1]);
            __half2 h = __floats2half2_rn(acc[nt][0], acc[nt][1]);
            *(__half2*)(Out16 + (size_t)r_lo * 128 + c) = h;
        }
        if (r_hi < n) {
            *(float2*)(Out + (size_t)r_hi * 128 + c) = make_float2(acc[nt][2], acc[nt][3]);
            __half2 h = __floats2half2_rn(acc[nt][2], acc[nt][3]);
            *(__half2*)(Out16 + (size_t)r_hi * 128 + c) = h;
        }
        float s_lo = acc[nt][0] * as0 + acc[nt][1] * as1;
        float d_lo = acc[nt][0] * ad0 + acc[nt][1] * ad1;
        float s_hi = acc[nt][2] * as0 + acc[nt][3] * as1;
        float d_hi = acc[nt][2] * ad0 + acc[nt][3] * ad1;
        if (nt < 4) { psA_lo += s_lo; pdA_lo += d_lo; psA_hi += s_hi; pdA_hi += d_hi; }
        else        { psB_lo += s_lo; pdB_lo += d_lo; psB_hi += s_hi; pdB_hi += d_hi; }
    }
    // reduce over the 4-lane quad (tig)
#pragma unroll
    for (int o = 1; o < 4; o <<= 1) {
        psA_lo += __shfl_xor_sync(0xffffffffu, psA_lo, o);
        psB_lo += __shfl_xor_sync(0xffffffffu, psB_lo, o);
        pdA_lo += __shfl_xor_sync(0xffffffffu, pdA_lo, o);
        pdB_lo += __shfl_xor_sync(0xffffffffu, pdB_lo, o);
        psA_hi += __shfl_xor_sync(0xffffffffu, psA_hi, o);
        psB_hi += __shfl_xor_sync(0xffffffffu, psB_hi, o);
        pdA_hi += __shfl_xor_sync(0xffffffffu, pdA_hi, o);
        pdB_hi += __shfl_xor_sync(0xffffffffu, pdB_hi, o);
    }
    if (tig == 0) {
        if (r_lo < n) {
            g_as[(size_t)r_lo * 4 + hA] = psA_lo;
            g_as[(size_t)r_lo * 4 + hB] = psB_lo;
            g_ad[(size_t)r_lo * 4 + hA] = pdA_lo;
            g_ad[(size_t)r_lo * 4 + hB] = pdB_lo;
            atomicMaxF(&smax[hA], psA_lo);
            atomicMaxF(&smax[hB], psB_lo);
        }
        if (r_hi < n) {
            g_as[(size_t)r_hi * 4 + hA] = psA_hi;
            g_as[(size_t)r_hi * 4 + hB] = psB_hi;
            g_ad[(size_t)r_hi * 4 + hA] = pdA_hi;
            g_ad[(size_t)r_hi * 4 + hB] = pdB_hi;
            atomicMaxF(&smax[hA], psA_hi);
            atomicMaxF(&smax[hB], psB_hi);
        }
    }
    __syncthreads();
    if (tid < NHEAD) atomicMaxF(&gmax4[tid], smax[tid]);
}

// ================= aggregate body =================
__device__ __forceinline__ void run_node(const float* __restrict__ b, float* __restrict__ outf,
                                         const float* __restrict__ gmax4,
                                         const float* __restrict__ sfw,
                                         const float* __restrict__ fcb, int n) {
    int w = (blockIdx.x * blockDim.x + threadIdx.x) >> 5;
    if (w >= n) return;
    int lane = threadIdx.x & 31;
    int head = lane >> 3;
    int hbase = lane & 24;
    int sub = lane & 7;

    int beg = g_rowptr[w];
    int end = g_rowptr[w + 1];

    float4 add4 = *(const float4*)(g_ad + (size_t)w * 4);
    float4 asd4 = *(const float4*)(g_as + (size_t)w * 4);
    float4 gm   = *(const float4*)gmax4;

    float adh = head == 0 ? add4.x : head == 1 ? add4.y : head == 2 ? add4.z : add4.w;
    float ash = head == 0 ? asd4.x : head == 1 ? asd4.y : head == 2 ? asd4.z : asd4.w;
    float gmh = head == 0 ? gm.x   : head == 1 ? gm.y   : head == 2 ? gm.z   : gm.w;
    float sh  = lrelu02(gmh + adh);

    float den = 0.f;
    float4 acc = make_float4(0.f, 0.f, 0.f, 0.f);

    for (int c = beg; c < end; c += 8) {
        int j = c + sub;
        int sidx = 0;
        float ex1 = 0.f;
        if (j < end) {
            sidx = g_csr_src[j];
            float a = g_as[(size_t)sidx * 4 + head];
            ex1 = __expf(lrelu02(a + adh) - sh);
        }
        den += ex1;
        int cnt = min(8, end - c);
        if (cnt == 8) {
            int   sk[8];
            float ek[8];
#pragma unroll
            for (int u = 0; u < 8; u++) {
                sk[u] = __shfl_sync(0xffffffffu, sidx, hbase + u);
                ek[u] = __shfl_sync(0xffffffffu, ex1,  hbase + u);
            }
            uint2 hv[8];
#pragma unroll
            for (int u = 0; u < 8; u++)
                hv[u] = ((const uint2*)(g_h16 + (size_t)sk[u] * 128))[lane];
#pragma unroll
            for (int u = 0; u < 8; u++) {
                float2 f0 = __half22float2(*(__half2*)&hv[u].x);
                float2 f1 = __half22float2(*(__half2*)&hv[u].y);
                acc.x += ek[u] * f0.x; acc.y += ek[u] * f0.y;
                acc.z += ek[u] * f1.x; acc.w += ek[u] * f1.y;
            }
        } else {
            for (int u = 0; u < cnt; u++) {
                int   sk = __shfl_sync(0xffffffffu, sidx, hbase + u);
                float ek = __shfl_sync(0xffffffffu, ex1,  hbase + u);
                uint2 hu = ((const uint2*)(g_h16 + (size_t)sk * 128))[lane];
                float2 f0 = __half22float2(*(__half2*)&hu.x);
                float2 f1 = __half22float2(*(__half2*)&hu.y);
                acc.x += ek * f0.x; acc.y += ek * f0.y;
                acc.z += ek * f1.x; acc.w += ek * f1.y;
            }
        }
    }
    den += __shfl_xor_sync(0xffffffffu, den, 1);
    den += __shfl_xor_sync(0xffffffffu, den, 2);
    den += __shfl_xor_sync(0xffffffffu, den, 4);

    float exs = __expf(lrelu02(ash + adh) - sh);
    den += exs;
    float inv = 1.f / (den + 1e-16f);

    float4 hself = ((const float4*)(g_h + (size_t)w * 128))[lane];
    float4 bv = ((const float4*)b)[lane];
    float4 o;
    o.x = (acc.x + exs * hself.x) * inv + bv.x;
    o.y = (acc.y + exs * hself.y) * inv + bv.y;
    o.z = (acc.z + exs * hself.z) * inv + bv.z;
    o.w = (acc.w + exs * hself.w) * inv + bv.w;
    o.x = o.x > 0.f ? o.x : expm1f(o.x);
    o.y = o.y > 0.f ? o.y : expm1f(o.y);
    o.z = o.z > 0.f ? o.z : expm1f(o.z);
    o.w = o.w > 0.f ? o.w : expm1f(o.w);

    if (sfw == nullptr) {
        ((float4*)(outf + (size_t)w * 128))[lane] = o;
    } else {
        float fa = fcb[lane];
#pragma unroll 8
        for (int r = 0; r < 32; r++) {
            float fx = __shfl_sync(0xffffffffu, o.x, r);
            float fy = __shfl_sync(0xffffffffu, o.y, r);
            float fz = __shfl_sync(0xffffffffu, o.z, r);
            float fw2 = __shfl_sync(0xffffffffu, o.w, r);
            int kb = r * 4;
            fa += fx * sfw[kb * 32 + lane] + fy * sfw[(kb + 1) * 32 + lane]
                + fz * sfw[(kb + 2) * 32 + lane] + fw2 * sfw[(kb + 3) * 32 + lane];
        }
        outf[(size_t)w * 32 + lane] = fa;
    }
}

template <bool FUSE>
__global__ void gat_aggregate(const float* __restrict__ b, float* __restrict__ outf,
                              const float* __restrict__ gmax4,
                              const float* __restrict__ fcw, const float* __restrict__ fcb,
                              int n) {
    if constexpr (FUSE) {
        __shared__ float sfw[HID * 32];
#pragma unroll
        for (int i = 0; i < 4; i++)
            ((float4*)sfw)[threadIdx.x + i * 256] = ((const float4*)fcw)[threadIdx.x + i * 256];
        __syncthreads();
        run_node(b, outf, gmax4, sfw, fcb, n);
    } else {
        run_node(b, outf, gmax4, (const float*)nullptr, fcb, n);
    }
}

// ================= launch =================
extern "C" void kernel_launch(void* const* d_in, const int* in_sizes, int n_in,
                              void* d_out, int out_size) {
    const float* x    = (const float*)d_in[0];
    const int*   ei   = (const int*)d_in[1];
    const float* W1   = (const float*)d_in[2];
    const float* a_s1 = (const float*)d_in[3];
    const float* a_d1 = (const float*)d_in[4];
    const float* b1   = (const float*)d_in[5];
    const float* W2   = (const float*)d_in[6];
    const float* a_s2 = (const float*)d_in[7];
    const float* a_d2 = (const float*)d_in[8];
    const float* b2   = (const float*)d_in[9];
    const float* fc_w = (const float*)d_in[10];
    const float* fc_b = (const float*)d_in[11];
    float* out = (float*)d_out;

    int n = in_sizes[0] / HID;
    int E = in_sizes[1] / 2;

    float *p_h, *p_feat, *p_gmax;
    __half* p_h16;
    cudaGetSymbolAddress((void**)&p_h, g_h);
    cudaGetSymbolAddress((void**)&p_h16, g_h16);
    cudaGetSymbolAddress((void**)&p_feat, g_feat);
    cudaGetSymbolAddress((void**)&p_gmax, g_gmax);

    static cudaStream_t sB = nullptr;
    static cudaEvent_t evF = nullptr, evJ = nullptr;
    if (sB == nullptr) {
        cudaStreamCreateWithFlags(&sB, cudaStreamNonBlocking);
        cudaEventCreateWithFlags(&evF, cudaEventDisableTiming);
        cudaEventCreateWithFlags(&evJ, cudaEventDisableTiming);
    }

    int gemm_grid = (n + 63) / 64;
    int warp_grid = (n * 32 + 255) / 256;
    int edge_grid = (E + 255) / 256;
    int node_grid = (n + 255) / 256;
    int scan_nb   = (n + SCAN_BLK - 1) / SCAN_BLK;

    k_init_gmax<<<1, 32>>>();

    // ---- fork: CSR build chain on sB, overlapped with gemm1 ----
    cudaEventRecord(evF, 0);
    cudaStreamWaitEvent(sB, evF, 0);
    k_zero_deg<<<node_grid, 256, 0, sB>>>(n);
    k_count<<<edge_grid, 256, 0, sB>>>(ei, E, n);
    k_scan_a<<<scan_nb, 256, 0, sB>>>(n);
    k_scan_b<<<1, 32, 0, sB>>>(scan_nb, n);
    k_scan_c<<<scan_nb, 256, 0, sB>>>(n);
    k_scatter<<<edge_grid, 256, 0, sB>>>(ei, E, n);
    cudaEventRecord(evJ, sB);

    // ---- layer 1 ----
    gemm128_tc<<<gemm_grid, 256>>>(x, W1, p_h, p_h16, a_s1, a_d1, p_gmax, n);
    cudaStreamWaitEvent(0, evJ, 0);
    gat_aggregate<false><<<warp_grid, 256>>>(b1, p_feat, p_gmax, nullptr, nullptr, n);

    // ---- layer 2 (FC fused into aggregation) ----
    gemm128_tc<<<gemm_grid, 256>>>(p_feat, W2, p_h, p_h16, a_s2, a_d2, p_gmax + 4, n);
    gat_aggregate<true><<<warp_grid, 256>>>(b2, out, p_gmax + 4, fc_w, fc_b, n);
}

// round 12
// speedup vs baseline: 2.1814x; 1.0186x over previous
#include <cuda_runtime.h>
#include <cuda_fp16.h>
#include <cstdint>

#define NMAX 50000
#define EMAX 800000
#define HID 128
#define NHEAD 4
#define SCAN_BLK 1024
#define SCAN_NB ((NMAX + SCAN_BLK - 1) / SCAN_BLK)

// ---------------- scratch (device globals; allocation-free) ----------------
__device__ float  g_h[(size_t)NMAX * HID];
__device__ __half g_h16[(size_t)NMAX * HID];
__device__ float  g_feat[(size_t)NMAX * HID];
__device__ float  g_as[(size_t)NMAX * NHEAD];
__device__ float  g_ad[(size_t)NMAX * NHEAD];
__device__ float  g_gmax[2 * NHEAD];
__device__ int    g_deg[NMAX];
__device__ int    g_rowptr[NMAX + 1];
__device__ int    g_cursor[NMAX];
__device__ int    g_csr_src[EMAX];
__device__ int    g_bsum[SCAN_NB];
__device__ int    g_boff[SCAN_NB];

__device__ __forceinline__ float lrelu02(float v) { return v > 0.f ? v : 0.2f * v; }

__device__ __forceinline__ void atomicMaxF(float* a, float v) {
    if (v >= 0.f) atomicMax((int*)a, __float_as_int(v));
    else          atomicMin((unsigned int*)a, __float_as_uint(v));
}

__device__ __forceinline__ unsigned f2tf32(float f) {
    unsigned u;
    asm("cvt.rna.tf32.f32 %0, %1;" : "=r"(u) : "f"(f));
    return u;
}

__device__ __forceinline__ void mma_tf32(float* c, unsigned a0, unsigned a1, unsigned a2,
                                         unsigned a3, unsigned b0, unsigned b1) {
    asm volatile(
        "mma.sync.aligned.m16n8k8.row.col.f32.tf32.tf32.f32 "
        "{%0,%1,%2,%3}, {%4,%5,%6,%7}, {%8,%9}, {%0,%1,%2,%3};"
        : "+f"(c[0]), "+f"(c[1]), "+f"(c[2]), "+f"(c[3])
        : "r"(a0), "r"(a1), "r"(a2), "r"(a3), "r"(b0), "r"(b1));
}

// ================= tiny init =================
__global__ void k_init_gmax() {
    if (threadIdx.x < 2 * NHEAD) g_gmax[threadIdx.x] = -1e30f;
}

// ================= CSR build (secondary stream) =================
__global__ void k_zero_deg(int n) {
    int i = blockIdx.x * blockDim.x + threadIdx.x;
    if (i < n) g_deg[i] = 0;
}

// 4 edges per thread, int4 loads of dst
__global__ void k_count(const int* __restrict__ ei, int E, int n) {
    int e4 = (blockIdx.x * blockDim.x + threadIdx.x) * 4;
    if (e4 + 3 < E) {
        int4 d = *(const int4*)(ei + (size_t)E + e4);
        if ((unsigned)d.x < (unsigned)n) atomicAdd(&g_deg[d.x], 1);
        if ((unsigned)d.y < (unsigned)n) atomicAdd(&g_deg[d.y], 1);
        if ((unsigned)d.z < (unsigned)n) atomicAdd(&g_deg[d.z], 1);
        if ((unsigned)d.w < (unsigned)n) atomicAdd(&g_deg[d.w], 1);
    } else {
        for (int e = e4; e < E; e++) {
            int d = ei[(size_t)E + e];
            if ((unsigned)d < (unsigned)n) atomicAdd(&g_deg[d], 1);
        }
    }
}

__global__ void k_scan_a(int n) {
    __shared__ int wsum[8];
    int base = blockIdx.x * SCAN_BLK + threadIdx.x * 4;
    int s = 0;
    if (base + 3 < n) {
        int4 v = *(const int4*)(g_deg + base);
        s = v.x + v.y + v.z + v.w;
    } else {
        for (int i = 0; i < 4; i++) if (base + i < n) s += g_deg[base + i];
    }
#pragma unroll
    for (int o = 16; o > 0; o >>= 1) s += __shfl_xor_sync(0xffffffffu, s, o);
    if ((threadIdx.x & 31) == 0) wsum[threadIdx.x >> 5] = s;
    __syncthreads();
    if (threadIdx.x == 0) {
        int t = 0;
#pragma unroll
        for (int i = 0; i < 8; i++) t += wsum[i];
        g_bsum[blockIdx.x] = t;
    }
}

__global__ void k_scan_b(int nb, int n) {
    if (threadIdx.x == 0) {
        int run = 0;
        for (int i = 0; i < nb; i++) {
            g_boff[i] = run;
            run += g_bsum[i];
        }
        g_rowptr[n] = run;
    }
}

__global__ void k_scan_c(int n) {
    __shared__ int woff[8];
    int tid = threadIdx.x;
    int base = blockIdx.x * SCAN_BLK + tid * 4;

    int d0 = 0, d1 = 0, d2 = 0, d3 = 0;
    if (base + 3 < n) {
        int4 v = *(const int4*)(g_deg + base);
        d0 = v.x; d1 = v.y; d2 = v.z; d3 = v.w;
    } else {
        if (base + 0 < n) d0 = g_deg[base + 0];
        if (base + 1 < n) d1 = g_deg[base + 1];
        if (base + 2 < n) d2 = g_deg[base + 2];
        if (base + 3 < n) d3 = g_deg[base + 3];
    }
    int ts = d0 + d1 + d2 + d3;

    int inc = ts;
#pragma unroll
    for (int o = 1; o < 32; o <<= 1) {
        int v = __shfl_up_sync(0xffffffffu, inc, o);
        if ((tid & 31) >= o) inc += v;
    }
    if ((tid & 31) == 31) woff[tid >> 5] = inc;
    __syncthreads();
    if (tid < 8) {
        int v = woff[tid];
        int e = 0;
        for (int i = 0; i < 8; i++) { int u = __shfl_sync(0xffu, v, i, 8); if (i < tid) e += u; }
        woff[tid] = e;
    }
    __syncthreads();
    int excl = inc - ts + woff[tid >> 5] + g_boff[blockIdx.x];

    int p0 = excl, p1 = p0 + d0, p2 = p1 + d1, p3 = p2 + d2;
    if (base + 3 < n) {
        int4 pv = make_int4(p0, p1, p2, p3);
        *(int4*)(g_rowptr + base) = pv;
        *(int4*)(g_cursor + base) = pv;
    } else {
        if (base + 0 < n) { g_rowptr[base + 0] = p0; g_cursor[base + 0] = p0; }
        if (base + 1 < n) { g_rowptr[base + 1] = p1; g_cursor[base + 1] = p1; }
        if (base + 2 < n) { g_rowptr[base + 2] = p2; g_cursor[base + 2] = p2; }
        if (base + 3 < n) { g_rowptr[base + 3] = p3; g_cursor[base + 3] = p3; }
    }
}

// 4 edges per thread, int4 loads of src & dst
__global__ void k_scatter(const int* __restrict__ ei, int E, int n) {
    int e4 = (blockIdx.x * blockDim.x + threadIdx.x) * 4;
    if (e4 + 3 < E) {
        int4 s = *(const int4*)(ei + e4);
        int4 d = *(const int4*)(ei + (size_t)E + e4);
        if ((unsigned)s.x < (unsigned)n && (unsigned)d.x < (unsigned)n)
            g_csr_src[atomicAdd(&g_cursor[d.x], 1)] = s.x;
        if ((unsigned)s.y < (unsigned)n && (unsigned)d.y < (unsigned)n)
            g_csr_src[atomicAdd(&g_cursor[d.y], 1)] = s.y;
        if ((unsigned)s.z < (unsigned)n && (unsigned)d.z < (unsigned)n)
            g_csr_src[atomicAdd(&g_cursor[d.z], 1)] = s.z;
        if ((unsigned)s.w < (unsigned)n && (unsigned)d.w < (unsigned)n)
            g_csr_src[atomicAdd(&g_cursor[d.w], 1)] = s.w;
    } else {
        for (int e = e4; e < E; e++) {
            int s = ei[e];
            int d = ei[(size_t)E + e];
            if ((unsigned)s < (unsigned)n && (unsigned)d < (unsigned)n)
                g_csr_src[atomicAdd(&g_cursor[d], 1)] = s;
        }
    }
}

// ================= tf32 tensor-core GEMM + alpha/gmax epilogue =================
__global__ void gemm128_tc(const float* __restrict__ A, const float* __restrict__ W,
                           float* __restrict__ Out, __half* __restrict__ Out16,
                           const float* __restrict__ a_s, const float* __restrict__ a_d,
                           float* __restrict__ gmax4, int n) {
    __shared__ unsigned xs[64 * 36];
    __shared__ unsigned ws[32 * 136];
    __shared__ float smax[NHEAD];
    int tid = threadIdx.x;
    int lane = tid & 31;
    int wid = tid >> 5;
    int gid = lane >> 2;
    int tig = lane & 3;
    int rw = wid >> 1;
    int cw = wid & 1;
    int row0 = blockIdx.x * 64;
    if (tid < NHEAD) smax[tid] = -1e30f;

    float acc[8][4];
#pragma unroll
    for (int nt = 0; nt < 8; nt++)
#pragma unroll
        for (int q = 0; q < 4; q++) acc[nt][q] = 0.f;

    for (int kc = 0; kc < 128; kc += 32) {
#pragma unroll
        for (int i = 0; i < 2; i++) {
            int idx = tid + i * 256;
            int r = idx >> 3;
            int kq = idx & 7;
            float4 v = make_float4(0.f, 0.f, 0.f, 0.f);
            if (row0 + r < n)
                v = *(const float4*)(A + (size_t)(row0 + r) * 128 + kc + kq * 4);
            uint4 u = make_uint4(f2tf32(v.x), f2tf32(v.y), f2tf32(v.z), f2tf32(v.w));
            *(uint4*)&xs[r * 36 + kq * 4] = u;
        }
#pragma unroll
        for (int i = 0; i < 4; i++) {
            int idx = tid + i * 256;
            int k = idx >> 5;
            int cq = idx & 31;
            float4 v = *(const float4*)(W + (size_t)(kc + k) * 128 + cq * 4);
            uint4 u = make_uint4(f2tf32(v.x), f2tf32(v.y), f2tf32(v.z), f2tf32(v.w));
            *(uint4*)&ws[k * 136 + cq * 4] = u;
        }
        __syncthreads();

        int ar0 = (rw * 16 + gid) * 36;
        int ar1 = (rw * 16 + gid + 8) * 36;
        int cb = cw * 64 + gid;
#pragma unroll
        for (int kk = 0; kk < 32; kk += 8) {
            unsigned a0 = xs[ar0 + kk + tig];
            unsigned a1 = xs[ar1 + kk + tig];
            unsigned a2 = xs[ar0 + kk + tig + 4];
            unsigned a3 = xs[ar1 + kk + tig + 4];
            int wr0 = (kk + tig) * 136;
            int wr1 = (kk + tig + 4) * 136;
#pragma unroll
            for (int nt = 0; nt < 8; nt++) {
                unsigned b0 = ws[wr0 + cb + nt * 8];
                unsigned b1 = ws[wr1 + cb + nt * 8];
                mma_tf32(acc[nt], a0, a1, a2, a3, b0, b1);
            }
        }
        __syncthreads();
    }

    int r_lo = row0 + rw * 16 + gid;
    int r_hi = r_lo + 8;
    int hA = 2 * cw, hB = 2 * cw + 1;

    float psA_lo = 0.f, psB_lo = 0.f, pdA_lo = 0.f, pdB_lo = 0.f;
    float psA_hi = 0.f, psB_hi = 0.f, pdA_hi = 0.f, pdB_hi = 0.f;

#pragma unroll
    for (int nt = 0; nt < 8; nt++) {
        int c = cw * 64 + nt * 8 + 2 * tig;
        float as0 = a_s[c], as1 = a_s[c + 1];
        float ad0 = a_d[c], ad1 = a_d[c + 1];
        if (r_lo < n) {
            *(float2*)(Out + (size_t)r_lo * 128 + c) = make_float2(acc[nt][0], acc[nt][1]);
            __half2 h = __floats2half2_rn(acc[nt][0], acc[nt][1]);
            *(__half2*)(Out16 + (size_t)r_lo * 128 + c) = h;
        }
        if (r_hi < n) {
            *(float2*)(Out + (size_t)r_hi * 128 + c) = make_float2(acc[nt][2], acc[nt][3]);
            __half2 h = __floats2half2_rn(acc[nt][2], acc[nt][3]);
            *(__half2*)(Out16 + (size_t)r_hi * 128 + c) = h;
        }
        float s_lo = acc[nt][0] * as0 + acc[nt][1] * as1;
        float d_lo = acc[nt][0] * ad0 + acc[nt][1] * ad1;
        float s_hi = acc[nt][2] * as0 + acc[nt][3] * as1;
        float d_hi = acc[nt][2] * ad0 + acc[nt][3] * ad1;
        if (nt < 4) { psA_lo += s_lo; pdA_lo += d_lo; psA_hi += s_hi; pdA_hi += d_hi; }
        else        { psB_lo += s_lo; pdB_lo += d_lo; psB_hi += s_hi; pdB_hi += d_hi; }
    }
#pragma unroll
    for (int o = 1; o < 4; o <<= 1) {
        psA_lo += __shfl_xor_sync(0xffffffffu, psA_lo, o);
        psB_lo += __shfl_xor_sync(0xffffffffu, psB_lo, o);
        pdA_lo += __shfl_xor_sync(0xffffffffu, pdA_lo, o);
        pdB_lo += __shfl_xor_sync(0xffffffffu, pdB_lo, o);
        psA_hi += __shfl_xor_sync(0xffffffffu, psA_hi, o);
        psB_hi += __shfl_xor_sync(0xffffffffu, psB_hi, o);
        pdA_hi += __shfl_xor_sync(0xffffffffu, pdA_hi, o);
        pdB_hi += __shfl_xor_sync(0xffffffffu, pdB_hi, o);
    }
    if (tig == 0) {
        if (r_lo < n) {
            g_as[(size_t)r_lo * 4 + hA] = psA_lo;
            g_as[(size_t)r_lo * 4 + hB] = psB_lo;
            g_ad[(size_t)r_lo * 4 + hA] = pdA_lo;
            g_ad[(size_t)r_lo * 4 + hB] = pdB_lo;
            atomicMaxF(&smax[hA], psA_lo);
            atomicMaxF(&smax[hB], psB_lo);
        }
        if (r_hi < n) {
            g_as[(size_t)r_hi * 4 + hA] = psA_hi;
            g_as[(size_t)r_hi * 4 + hB] = psB_hi;
            g_ad[(size_t)r_hi * 4 + hA] = pdA_hi;
            g_ad[(size_t)r_hi * 4 + hB] = pdB_hi;
            atomicMaxF(&smax[hA], psA_hi);
            atomicMaxF(&smax[hB], psB_hi);
        }
    }
    __syncthreads();
    if (tid < NHEAD) atomicMaxF(&gmax4[tid], smax[tid]);
}

// ================= aggregate body (software-pipelined) =================
__device__ __forceinline__ void run_node(const float* __restrict__ b, float* __restrict__ outf,
                                         const float* __restrict__ gmax4,
                                         const float* __restrict__ sfw,
                                         const float* __restrict__ fcb, int n) {
    int w = (blockIdx.x * blockDim.x + threadIdx.x) >> 5;
    if (w >= n) return;
    int lane = threadIdx.x & 31;
    int head = lane >> 3;
    int hbase = lane & 24;
    int sub = lane & 7;

    int beg = g_rowptr[w];
    int end = g_rowptr[w + 1];

    float4 add4 = *(const float4*)(g_ad + (size_t)w * 4);
    float4 asd4 = *(const float4*)(g_as + (size_t)w * 4);
    float4 gm   = *(const float4*)gmax4;

    float adh = head == 0 ? add4.x : head == 1 ? add4.y : head == 2 ? add4.z : add4.w;
    float ash = head == 0 ? asd4.x : head == 1 ? asd4.y : head == 2 ? asd4.z : asd4.w;
    float gmh = head == 0 ? gm.x   : head == 1 ? gm.y   : head == 2 ? gm.z   : gm.w;
    float sh  = lrelu02(gmh + adh);

    float den = 0.f;
    float4 acc = make_float4(0.f, 0.f, 0.f, 0.f);

    // prologue: prefetch first group's src index + alpha
    int sidx_n = 0;
    float a_n = 0.f;
    {
        int j = beg + sub;
        if (j < end) {
            sidx_n = g_csr_src[j];
            a_n = g_as[(size_t)sidx_n * 4 + head];
        }
    }

    for (int c = beg; c < end; c += 8) {
        int sidx = sidx_n;
        float a = a_n;
        bool valid = (c + sub) < end;
        // prefetch next group (overlaps with shuffles/gathers below)
        int jn = c + 8 + sub;
        if (jn < end) {
            sidx_n = g_csr_src[jn];
            a_n = g_as[(size_t)sidx_n * 4 + head];
        }
        float ex1 = valid ? __expf(lrelu02(a + adh) - sh) : 0.f;
        den += ex1;

        int cnt = min(8, end - c);
        if (cnt == 8) {
            int   sk[8];
            float ek[8];
#pragma unroll
            for (int u = 0; u < 8; u++) {
                sk[u] = __shfl_sync(0xffffffffu, sidx, hbase + u);
                ek[u] = __shfl_sync(0xffffffffu, ex1,  hbase + u);
            }
            uint2 hv[8];
#pragma unroll
            for (int u = 0; u < 8; u++)
                hv[u] = ((const uint2*)(g_h16 + (size_t)sk[u] * 128))[lane];
#pragma unroll
            for (int u = 0; u < 8; u++) {
                float2 f0 = __half22float2(*(__half2*)&hv[u].x);
                float2 f1 = __half22float2(*(__half2*)&hv[u].y);
                acc.x += ek[u] * f0.x; acc.y += ek[u] * f0.y;
                acc.z += ek[u] * f1.x; acc.w += ek[u] * f1.y;
            }
        } else {
            for (int u = 0; u < cnt; u++) {
                int   sk = __shfl_sync(0xffffffffu, sidx, hbase + u);
                float ek = __shfl_sync(0xffffffffu, ex1,  hbase + u);
                uint2 hu = ((const uint2*)(g_h16 + (size_t)sk * 128))[lane];
                float2 f0 = __half22float2(*(__half2*)&hu.x);
                float2 f1 = __half22float2(*(__half2*)&hu.y);
                acc.x += ek * f0.x; acc.y += ek * f0.y;
                acc.z += ek * f1.x; acc.w += ek * f1.y;
            }
        }
    }
    den += __shfl_xor_sync(0xffffffffu, den, 1);
    den += __shfl_xor_sync(0xffffffffu, den, 2);
    den += __shfl_xor_sync(0xffffffffu, den, 4);

    float exs = __expf(lrelu02(ash + adh) - sh);
    den += exs;
    float inv = 1.f / (den + 1e-16f);

    float4 hself = ((const float4*)(g_h + (size_t)w * 128))[lane];
    float4 bv = ((const float4*)b)[lane];
    float4 o;
    o.x = (acc.x + exs * hself.x) * inv + bv.x;
    o.y = (acc.y + exs * hself.y) * inv + bv.y;
    o.z = (acc.z + exs * hself.z) * inv + bv.z;
    o.w = (acc.w + exs * hself.w) * inv + bv.w;
    o.x = o.x > 0.f ? o.x : expm1f(o.x);
    o.y = o.y > 0.f ? o.y : expm1f(o.y);
    o.z = o.z > 0.f ? o.z : expm1f(o.z);
    o.w = o.w > 0.f ? o.w : expm1f(o.w);

    if (sfw == nullptr) {
        ((float4*)(outf + (size_t)w * 128))[lane] = o;
    } else {
        float fa = fcb[lane];
#pragma unroll 8
        for (int r = 0; r < 32; r++) {
            float fx = __shfl_sync(0xffffffffu, o.x, r);
            float fy = __shfl_sync(0xffffffffu, o.y, r);
            float fz = __shfl_sync(0xffffffffu, o.z, r);
            float fw2 = __shfl_sync(0xffffffffu, o.w, r);
            int kb = r * 4;
            fa += fx * sfw[kb * 32 + lane] + fy * sfw[(kb + 1) * 32 + lane]
                + fz * sfw[(kb + 2) * 32 + lane] + fw2 * sfw[(kb + 3) * 32 + lane];
        }
        outf[(size_t)w * 32 + lane] = fa;
    }
}

template <bool FUSE>
__global__ void gat_aggregate(const float* __restrict__ b, float* __restrict__ outf,
                              const float* __restrict__ gmax4,
                              const float* __restrict__ fcw, const float* __restrict__ fcb,
                              int n) {
    if constexpr (FUSE) {
        __shared__ float sfw[HID * 32];
#pragma unroll
        for (int i = 0; i < 4; i++)
            ((float4*)sfw)[threadIdx.x + i * 256] = ((const float4*)fcw)[threadIdx.x + i * 256];
        __syncthreads();
        run_node(b, outf, gmax4, sfw, fcb, n);
    } else {
        run_node(b, outf, gmax4, (const float*)nullptr, fcb, n);
    }
}

// ================= launch =================
extern "C" void kernel_launch(void* const* d_in, const int* in_sizes, int n_in,
                              void* d_out, int out_size) {
    const float* x    = (const float*)d_in[0];
    const int*   ei   = (const int*)d_in[1];
    const float* W1   = (const float*)d_in[2];
    const float* a_s1 = (const float*)d_in[3];
    const float* a_d1 = (const float*)d_in[4];
    const float* b1   = (const float*)d_in[5];
    const float* W2   = (const float*)d_in[6];
    const float* a_s2 = (const float*)d_in[7];
    const float* a_d2 = (const float*)d_in[8];
    const float* b2   = (const float*)d_in[9];
    const float* fc_w = (const float*)d_in[10];
    const float* fc_b = (const float*)d_in[11];
    float* out = (float*)d_out;

    int n = in_sizes[0] / HID;
    int E = in_sizes[1] / 2;

    float *p_h, *p_feat, *p_gmax;
    __half* p_h16;
    cudaGetSymbolAddress((void**)&p_h, g_h);
    cudaGetSymbolAddress((void**)&p_h16, g_h16);
    cudaGetSymbolAddress((void**)&p_feat, g_feat);
    cudaGetSymbolAddress((void**)&p_gmax, g_gmax);

    static cudaStream_t sB = nullptr;
    static cudaEvent_t evF = nullptr, evJ = nullptr;
    if (sB == nullptr) {
        cudaStreamCreateWithFlags(&sB, cudaStreamNonBlocking);
        cudaEventCreateWithFlags(&evF, cudaEventDisableTiming);
        cudaEventCreateWithFlags(&evJ, cudaEventDisableTiming);
    }

    int gemm_grid = (n + 63) / 64;
    int warp_grid = (n * 32 + 255) / 256;
    int edge4_grid = ((E + 3) / 4 + 255) / 256;
    int node_grid = (n + 255) / 256;
    int scan_nb   = (n + SCAN_BLK - 1) / SCAN_BLK;

    k_init_gmax<<<1, 32>>>();

    // ---- fork: CSR build chain on sB, overlapped with gemm1 ----
    cudaEventRecord(evF, 0);
    cudaStreamWaitEvent(sB, evF, 0);
    k_zero_deg<<<node_grid, 256, 0, sB>>>(n);
    k_count<<<edge4_grid, 256, 0, sB>>>(ei, E, n);
    k_scan_a<<<scan_nb, 256, 0, sB>>>(n);
    k_scan_b<<<1, 32, 0, sB>>>(scan_nb, n);
    k_scan_c<<<scan_nb, 256, 0, sB>>>(n);
    k_scatter<<<edge4_grid, 256, 0, sB>>>(ei, E, n);
    cudaEventRecord(evJ, sB);

    // ---- layer 1 ----
    gemm128_tc<<<gemm_grid, 256>>>(x, W1, p_h, p_h16, a_s1, a_d1, p_gmax, n);
    cudaStreamWaitEvent(0, evJ, 0);
    gat_aggregate<false><<<warp_grid, 256>>>(b1, p_feat, p_gmax, nullptr, nullptr, n);

    // ---- layer 2 (FC fused into aggregation) ----
    gemm128_tc<<<gemm_grid, 256>>>(p_feat, W2, p_h, p_h16, a_s2, a_d2, p_gmax + 4, n);
    gat_aggregate<true><<<warp_grid, 256>>>(b2, out, p_gmax + 4, fc_w, fc_b, n);
}